// round 11
// baseline (speedup 1.0000x reference)
#include <cuda_runtime.h>
#include <cuda_bf16.h>
#include <math.h>
#include <stdint.h>

#define DIM      128
#define N_DIAG   30000
#define N_PRO    20000
#define N_NODES  50000
#define N_EDGES  800000
#define N_REL    8
#define T_VISITS 2
#define NCOLS    (N_REL * DIM + DIM)   // 1152
#define NRD      (N_REL * DIM)         // 1024
#define VOC_DIAG 2000
#define VOC_PRO  1500
#define TAB_ROWS (VOC_DIAG + VOC_PRO)  // 3500
#define VOC3     150

// RULES LEARNED (hard way):
//  1. NO CUDA API calls before main().
//  2. NO register caps that cause spills (local-pool growth trips mem checkpoint).
//  3. From HOST code, pass device globals via cudaGetSymbolAddress, never by name.
__device__ __align__(16) float g_x  [N_NODES * DIM];                 // layer output (relu'd)
__device__ __align__(16) float g_agg[(size_t)N_NODES * NRD];         // layer-2 aggregates
__device__ __align__(16) float g_tab[TAB_ROWS * NCOLS];              // layer-1 dedup table
__device__ __align__(16) int   g_map[N_NODES];                       // node -> table row
__device__ __align__(16) int   g_cnt[N_NODES * N_REL];               // (dst,rel) counts
__device__ __align__(16) int   g_off[N_NODES + 1];                   // CSR row offsets
__device__ __align__(16) int   g_pos[N_NODES];                       // scatter cursors
__device__ __align__(16) int   g_epk[N_EDGES];                       // packed src|et|map
__device__ __align__(16) float g_Wbig[DIM * NCOLS];                  // layer-1 repacked W
__device__ __align__(16) float g_cread[DIM];
__device__ __align__(16) float g_h[DIM];

// ---------------- packed fp32 helpers (Blackwell FFMA2 via PTX f32x2) ----------------
__device__ __forceinline__ unsigned long long fma2(unsigned long long a,
                                                   unsigned long long b,
                                                   unsigned long long c)
{
    unsigned long long d;
    asm("fma.rn.f32x2 %0, %1, %2, %3;" : "=l"(d) : "l"(a), "l"(b), "l"(c));
    return d;
}
__device__ __forceinline__ float2 u2f(unsigned long long u)
{
    float2 f;
    asm("mov.b64 {%0, %1}, %2;" : "=f"(f.x), "=f"(f.y) : "l"(u));
    return f;
}

// ---------------- repack W1: Wbig[d*1152 + c] = [W1_r | root1] ----------------
__global__ void prep_wbig_kernel(const float* __restrict__ W,
                                 const float* __restrict__ root,
                                 float* __restrict__ out)
{
    int idx = blockIdx.x * blockDim.x + threadIdx.x;
    if (idx >= DIM * NCOLS) return;
    int d = idx / NCOLS;
    int c = idx % NCOLS;
    float v;
    if (c < NRD) {
        int r = c >> 7, o = c & 127;
        v = W[(size_t)r * DIM * DIM + d * DIM + o];
    } else {
        v = root[d * DIM + (c - NRD)];
    }
    out[idx] = v;
}

// ---------------- node -> embedding-table row map ----------------
__global__ void map_kernel(const int* __restrict__ diag_idx,
                           const int* __restrict__ pro_idx)
{
    int n = blockIdx.x * blockDim.x + threadIdx.x;
    if (n >= N_NODES) return;
    int m;
    if (n < N_DIAG) m = min(max(diag_idx[n], 0), VOC_DIAG - 1);
    else            m = VOC_DIAG + min(max(pro_idx[n - N_DIAG], 0), VOC_PRO - 1);
    g_map[n] = m;
}

// ---------------- histogram of (dst, etype) ----------------
__global__ void hist_kernel(const int* __restrict__ dst, const int* __restrict__ et)
{
    int e = blockIdx.x * blockDim.x + threadIdx.x;
    if (e >= N_EDGES) return;
    int d = min(max(dst[e], 0), N_NODES - 1);
    int r = et[e] & (N_REL - 1);
    atomicAdd(&g_cnt[d * N_REL + r], 1);
}

// ---------------- exclusive prefix scan of per-dst edge totals (1 block) -------------
#define SCAN_T 1024
__global__ __launch_bounds__(SCAN_T)
void scan_kernel()
{
    __shared__ int sdata[SCAN_T];
    __shared__ int carry;
    int tid = threadIdx.x;
    if (tid == 0) carry = 0;
    __syncthreads();
    for (int base = 0; base < N_NODES; base += SCAN_T) {
        int d = base + tid;
        int v = 0;
        if (d < N_NODES) {
#pragma unroll
            for (int r = 0; r < N_REL; r++) v += g_cnt[d * N_REL + r];
        }
        sdata[tid] = v;
        __syncthreads();
        for (int ofs = 1; ofs < SCAN_T; ofs <<= 1) {
            int t = (tid >= ofs) ? sdata[tid - ofs] : 0;
            __syncthreads();
            sdata[tid] += t;
            __syncthreads();
        }
        int incl = sdata[tid];
        int excl = incl - v;
        if (d < N_NODES) {
            g_off[d] = carry + excl;
            g_pos[d] = carry + excl;
        }
        __syncthreads();
        if (tid == SCAN_T - 1) carry += incl;
        __syncthreads();
    }
    if (tid == 0) g_off[N_NODES] = carry;
}

// ---------------- scatter edges into CSR; pack src|et|map[src] ----------------
__global__ void scatter_kernel(const int* __restrict__ src, const int* __restrict__ dst,
                               const int* __restrict__ et)
{
    int e = blockIdx.x * blockDim.x + threadIdx.x;
    if (e >= N_EDGES) return;
    int d = min(max(__ldg(dst + e), 0), N_NODES - 1);
    int s = min(max(__ldg(src + e), 0), N_NODES - 1);
    int r = __ldg(et + e) & (N_REL - 1);
    int m = __ldg(&g_map[s]);
    int p = atomicAdd(&g_pos[d], 1);
    g_epk[p] = s | (r << 16) | (m << 19);
}

// ---------------- layer-1 CSR gather from L2-resident tab (root+relu fused) -------
#define GATHER_BLOCKS ((N_NODES + 7) / 8)
__global__ __launch_bounds__(256)
void gather_kernel()
{
    int gw   = (blockIdx.x * 256 + threadIdx.x) >> 5;
    int lane = threadIdx.x & 31;
    if (gw >= N_NODES) return;
    const int d = gw;

    int b  = __ldg(&g_off[d]);
    int e2 = __ldg(&g_off[d + 1]);

    float nv = 0.f;
    if (lane < N_REL) {
        int c = __ldg(&g_cnt[d * N_REL + lane]);
        nv = 1.0f / (float)max(c, 1);
    }

    float4 acc = make_float4(0.f, 0.f, 0.f, 0.f);

#define GACC(pk) do {                                                        \
        int s_ = (pk) >> 19;                                                  \
        int r_ = ((pk) >> 16) & 7;                                           \
        float nm = __shfl_sync(0xFFFFFFFFu, nv, r_);                          \
        float4 v_ = *(const float4*)(g_tab + (size_t)s_ * NCOLS              \
                                     + r_ * DIM + lane * 4);                  \
        acc.x += v_.x * nm; acc.y += v_.y * nm;                               \
        acc.z += v_.z * nm; acc.w += v_.w * nm;                               \
    } while (0)

    int i = b;
    for (; i + 4 <= e2; i += 4) {
        int pk0 = __ldg(g_epk + i + 0);
        int pk1 = __ldg(g_epk + i + 1);
        int pk2 = __ldg(g_epk + i + 2);
        int pk3 = __ldg(g_epk + i + 3);
        GACC(pk0); GACC(pk1); GACC(pk2); GACC(pk3);
    }
    for (; i < e2; i++) { int pk = __ldg(g_epk + i); GACC(pk); }
#undef GACC

    int m = __ldg(&g_map[d]);
    float4 base = *(const float4*)(g_tab + (size_t)m * NCOLS + NRD + lane * 4);
    float4 o;
    o.x = fmaxf(base.x + acc.x, 0.f);
    o.y = fmaxf(base.y + acc.y, 0.f);
    o.z = fmaxf(base.z + acc.z, 0.f);
    o.w = fmaxf(base.w + acc.w, 0.f);
    *(float4*)(g_x + (size_t)d * DIM + lane * 4) = o;
}

// ---------------- layer-2 aggregate-first: agg[d,r*128+..] = norm * sum x[src] -------
__global__ __launch_bounds__(256)
void agg_kernel()
{
    int gw   = (blockIdx.x * 256 + threadIdx.x) >> 5;
    int lane = threadIdx.x & 31;
    if (gw >= N_NODES) return;
    const int d = gw;

    int b  = __ldg(&g_off[d]);
    int e2 = __ldg(&g_off[d + 1]);

    float nv = 0.f;
    if (lane < N_REL) {
        int c = __ldg(&g_cnt[d * N_REL + lane]);
        nv = 1.0f / (float)max(c, 1);
    }

    float4 a0 = {0,0,0,0}, a1 = {0,0,0,0}, a2 = {0,0,0,0}, a3 = {0,0,0,0};
    float4 a4 = {0,0,0,0}, a5 = {0,0,0,0}, a6 = {0,0,0,0}, a7 = {0,0,0,0};

#define AACC(pk) do {                                                         \
        int s_ = (pk) & 0xFFFF;                                               \
        int r_ = ((pk) >> 16) & 7;                                           \
        float4 v_ = *(const float4*)(g_x + (size_t)s_ * DIM + lane * 4);      \
        switch (r_) {                                                         \
        case 0: a0.x+=v_.x; a0.y+=v_.y; a0.z+=v_.z; a0.w+=v_.w; break;        \
        case 1: a1.x+=v_.x; a1.y+=v_.y; a1.z+=v_.z; a1.w+=v_.w; break;        \
        case 2: a2.x+=v_.x; a2.y+=v_.y; a2.z+=v_.z; a2.w+=v_.w; break;        \
        case 3: a3.x+=v_.x; a3.y+=v_.y; a3.z+=v_.z; a3.w+=v_.w; break;        \
        case 4: a4.x+=v_.x; a4.y+=v_.y; a4.z+=v_.z; a4.w+=v_.w; break;        \
        case 5: a5.x+=v_.x; a5.y+=v_.y; a5.z+=v_.z; a5.w+=v_.w; break;        \
        case 6: a6.x+=v_.x; a6.y+=v_.y; a6.z+=v_.z; a6.w+=v_.w; break;        \
        default:a7.x+=v_.x; a7.y+=v_.y; a7.z+=v_.z; a7.w+=v_.w; break;        \
        }                                                                     \
    } while (0)

    int i = b;
    for (; i + 4 <= e2; i += 4) {
        int pk0 = __ldg(g_epk + i + 0);
        int pk1 = __ldg(g_epk + i + 1);
        int pk2 = __ldg(g_epk + i + 2);
        int pk3 = __ldg(g_epk + i + 3);
        AACC(pk0); AACC(pk1); AACC(pk2); AACC(pk3);
    }
    for (; i < e2; i++) { int pk = __ldg(g_epk + i); AACC(pk); }
#undef AACC

    float* dstp = g_agg + (size_t)d * NRD + lane * 4;
#define ASTORE(r_, a_) do {                                                   \
        float nm = __shfl_sync(0xFFFFFFFFu, nv, r_);                          \
        float4 o_ = make_float4(a_.x*nm, a_.y*nm, a_.z*nm, a_.w*nm);          \
        *(float4*)(dstp + r_ * DIM) = o_;                                     \
    } while (0)
    ASTORE(0, a0); ASTORE(1, a1); ASTORE(2, a2); ASTORE(3, a3);
    ASTORE(4, a4); ASTORE(5, a5); ASTORE(6, a6); ASTORE(7, a7);
#undef ASTORE
}

// ======== table GEMM (3500 rows; small, plain-FMA form) ====
#define T_BM 128
#define T_BN 64
#define T_BK 32
#define TAB_GRID_X (NCOLS / T_BN)                      // 18
#define TAB_GRID_Y ((TAB_ROWS + T_BM - 1) / T_BM)      // 28
__global__ __launch_bounds__(256)
void tabgemm_kernel(const float* __restrict__ diag_emb,
                    const float* __restrict__ pro_emb,
                    const float* __restrict__ Bmat,
                    const float* __restrict__ bias)
{
    __shared__ float As[T_BK][T_BM + 4];
    __shared__ float Bs[T_BK][T_BN];

    const int block_m = blockIdx.y * T_BM;
    const int block_n = blockIdx.x * T_BN;
    const int tid = threadIdx.x;
    const int tx = tid & 15;
    const int ty = tid >> 4;

    float acc[8][4];
#pragma unroll
    for (int m = 0; m < 8; m++)
#pragma unroll
        for (int n = 0; n < 4; n++) acc[m][n] = 0.f;

    for (int kb = 0; kb < DIM; kb += T_BK) {
#pragma unroll
        for (int i = 0; i < 4; i++) {
            int fid = tid + i * 256;
            int r   = fid >> 3;
            int c   = (fid & 7) * 4;
            int row = block_m + r;
            float4 v = make_float4(0.f, 0.f, 0.f, 0.f);
            if (row < TAB_ROWS) {
                const float* srow = (row < VOC_DIAG)
                    ? diag_emb + (size_t)row * DIM
                    : pro_emb  + (size_t)(row - VOC_DIAG) * DIM;
                v = *(const float4*)(srow + kb + c);
            }
            As[c + 0][r] = v.x; As[c + 1][r] = v.y;
            As[c + 2][r] = v.z; As[c + 3][r] = v.w;
        }
#pragma unroll
        for (int i = 0; i < 2; i++) {
            int fid = tid + i * 256;
            int r   = fid >> 4;
            int c   = (fid & 15) * 4;
            *(float4*)(&Bs[r][c]) =
                *(const float4*)(Bmat + (size_t)(kb + r) * NCOLS + block_n + c);
        }
        __syncthreads();

#pragma unroll
        for (int k = 0; k < T_BK; k++) {
            float4 a0 = *(const float4*)(&As[k][ty * 8]);
            float4 a1 = *(const float4*)(&As[k][ty * 8 + 4]);
            float4 b  = *(const float4*)(&Bs[k][tx * 4]);
            float am[8] = {a0.x, a0.y, a0.z, a0.w, a1.x, a1.y, a1.z, a1.w};
#pragma unroll
            for (int m = 0; m < 8; m++) {
                acc[m][0] = fmaf(am[m], b.x, acc[m][0]);
                acc[m][1] = fmaf(am[m], b.y, acc[m][1]);
                acc[m][2] = fmaf(am[m], b.z, acc[m][2]);
                acc[m][3] = fmaf(am[m], b.w, acc[m][3]);
            }
        }
        __syncthreads();
    }

    const int col = block_n + tx * 4;
#pragma unroll
    for (int m = 0; m < 8; m++) {
        int row = block_m + ty * 8 + m;
        if (row >= TAB_ROWS) continue;
        float4 v = make_float4(acc[m][0], acc[m][1], acc[m][2], acc[m][3]);
        if (col >= NRD) {
            float4 bv = *(const float4*)(bias + (col - NRD));
            v.x += bv.x; v.y += bv.y; v.z += bv.z; v.w += bv.w;
        }
        *(float4*)(g_tab + (size_t)row * NCOLS + col) = v;
    }
}

// ======== layer-2 GEMM: [50000,1152] x [1152,128], FFMA2, fused bias+relu+readout ====
// A = [g_agg | g_x]; B = [W2 rows | root2 rows] (native layouts, no repack).
// Each block reads only its OWN rows of g_x and writes only its own rows -> safe.
#define BM 128
#define BN 128
#define BK 16
#define GEMM2_GRID ((N_NODES + BM - 1) / BM)           // 391
__global__ __launch_bounds__(256)
void gemm2_kernel(const float* __restrict__ W2, const float* __restrict__ root2,
                  const float* __restrict__ bias)
{
    __shared__ float As2[BK][2 * BM + 8];
    __shared__ float Bs [BK][BN + 4];
    __shared__ float colsum[BN];

    const int block_m = blockIdx.x * BM;
    const int tid = threadIdx.x;
    const int tx = tid & 15;
    const int ty = tid >> 4;

    unsigned long long acc2[8][4];
#pragma unroll
    for (int m = 0; m < 8; m++)
#pragma unroll
        for (int n = 0; n < 4; n++) acc2[m][n] = 0ull;

    for (int kb = 0; kb < NCOLS; kb += BK) {
        // A tile: 128 rows x 16 k (agg for kb<1024, x for kb>=1024), duplicated
#pragma unroll
        for (int i = 0; i < 2; i++) {
            int fid = tid + i * 256;
            int r   = fid >> 2;
            int c   = (fid & 3) * 4;
            int row = block_m + r;
            float4 v = make_float4(0.f, 0.f, 0.f, 0.f);
            if (row < N_NODES) {
                if (kb < NRD)
                    v = *(const float4*)(g_agg + (size_t)row * NRD + kb + c);
                else
                    v = *(const float4*)(g_x + (size_t)row * DIM + (kb - NRD) + c);
            }
            *(float2*)(&As2[c + 0][2 * r]) = make_float2(v.x, v.x);
            *(float2*)(&As2[c + 1][2 * r]) = make_float2(v.y, v.y);
            *(float2*)(&As2[c + 2][2 * r]) = make_float2(v.z, v.z);
            *(float2*)(&As2[c + 3][2 * r]) = make_float2(v.w, v.w);
        }
        // B tile: 16 k-rows x 128 n  (W2 rows then root2 rows)
#pragma unroll
        for (int i = 0; i < 2; i++) {
            int fid = tid + i * 256;
            int r   = fid >> 5;
            int c   = (fid & 31) * 4;
            int k   = kb + r;
            const float* brow = (k < NRD) ? (W2 + (size_t)k * DIM)
                                          : (root2 + (size_t)(k - NRD) * DIM);
            *(float4*)(&Bs[r][c]) = *(const float4*)(brow + c);
        }
        __syncthreads();

#pragma unroll
        for (int k = 0; k < BK; k++) {
            const ulonglong2* ap = (const ulonglong2*)(&As2[k][ty * 16]);
            ulonglong2 a01 = ap[0], a23 = ap[1], a45 = ap[2], a67 = ap[3];
            const ulonglong2* bp = (const ulonglong2*)(&Bs[k][tx * 8]);
            ulonglong2 bA = bp[0], bB = bp[1];
            unsigned long long am[8] = {a01.x, a01.y, a23.x, a23.y,
                                        a45.x, a45.y, a67.x, a67.y};
#pragma unroll
            for (int m = 0; m < 8; m++) {
                acc2[m][0] = fma2(am[m], bA.x, acc2[m][0]);
                acc2[m][1] = fma2(am[m], bA.y, acc2[m][1]);
                acc2[m][2] = fma2(am[m], bB.x, acc2[m][2]);
                acc2[m][3] = fma2(am[m], bB.y, acc2[m][3]);
            }
        }
        __syncthreads();
    }

    // epilogue: bias + relu -> g_x; column partial sums -> g_cread
    if (tid < BN) colsum[tid] = 0.f;
    __syncthreads();

    const int col0 = tx * 8;
    float4 b0 = *(const float4*)(bias + col0);
    float4 b1 = *(const float4*)(bias + col0 + 4);
    float cs[8] = {0,0,0,0,0,0,0,0};
#pragma unroll
    for (int m = 0; m < 8; m++) {
        int row = block_m + ty * 8 + m;
        if (row >= N_NODES) continue;
        float2 p0 = u2f(acc2[m][0]), p1 = u2f(acc2[m][1]);
        float2 p2 = u2f(acc2[m][2]), p3 = u2f(acc2[m][3]);
        float o[8] = {p0.x + b0.x, p0.y + b0.y, p1.x + b0.z, p1.y + b0.w,
                      p2.x + b1.x, p2.y + b1.y, p3.x + b1.z, p3.y + b1.w};
#pragma unroll
        for (int j = 0; j < 8; j++) { o[j] = fmaxf(o[j], 0.f); cs[j] += o[j]; }
        float4* dst = (float4*)(g_x + (size_t)row * DIM + col0);
        dst[0] = make_float4(o[0], o[1], o[2], o[3]);
        dst[1] = make_float4(o[4], o[5], o[6], o[7]);
    }
#pragma unroll
    for (int j = 0; j < 8; j++) atomicAdd(&colsum[col0 + j], cs[j]);
    __syncthreads();
    if (tid < BN) atomicAdd(&g_cread[tid], colsum[tid]);
}

// ---------------- GRU cell (single block, 128 threads) ----------------
__global__ void gru_kernel(const float* __restrict__ Wih, const float* __restrict__ Whh,
                           const float* __restrict__ bih, const float* __restrict__ bhh)
{
    __shared__ float c[DIM], hh[DIM];
    int tid = threadIdx.x;
    c[tid]  = g_cread[tid];
    hh[tid] = g_h[tid];
    __syncthreads();

    float gi[3], gh[3];
#pragma unroll
    for (int g = 0; g < 3; g++) {
        int row = g * DIM + tid;
        float si = bih[row], sh = bhh[row];
        const float* wi = Wih + (size_t)row * DIM;
        const float* wh = Whh + (size_t)row * DIM;
        for (int d = 0; d < DIM; d++) {
            si = fmaf(c[d],  wi[d], si);
            sh = fmaf(hh[d], wh[d], sh);
        }
        gi[g] = si; gh[g] = sh;
    }
    float r = 1.0f / (1.0f + expf(-(gi[0] + gh[0])));
    float z = 1.0f / (1.0f + expf(-(gi[1] + gh[1])));
    float n = tanhf(gi[2] + r * gh[2]);
    float hn = (1.0f - z) * n + z * hh[tid];
    __syncthreads();
    g_h[tid] = hn;
}

// ---------------- output head (single block, 256 threads) ----------------
__global__ void out_kernel(const float* __restrict__ Wo1, const float* __restrict__ bo1,
                           const float* __restrict__ Wo2, const float* __restrict__ bo2,
                           float* __restrict__ out)
{
    __shared__ float hs[DIM], tmp[2 * DIM];
    int tid = threadIdx.x;
    if (tid < DIM) hs[tid] = g_h[tid];
    __syncthreads();
    {
        float a = bo1[tid];
        const float* w = Wo1 + (size_t)tid * DIM;
        for (int d = 0; d < DIM; d++) a = fmaf(hs[d], w[d], a);
        tmp[tid] = fmaxf(a, 0.f);
    }
    __syncthreads();
    if (tid < VOC3) {
        float o = bo2[tid];
        const float* w = Wo2 + (size_t)tid * 2 * DIM;
        for (int j = 0; j < 2 * DIM; j++) o = fmaf(tmp[j], w[j], o);
        out[tid] = o;
    }
}

// =============================== host launcher ===============================
extern "C" void kernel_launch(void* const* d_in, const int* in_sizes, int n_in,
                              void* d_out, int out_size)
{
    const int*   c_diag_idx   = (const int*)  d_in[0];
    const int*   c_pro_idx    = (const int*)  d_in[1];
    const int*   c_edge_index = (const int*)  d_in[2];
    const int*   c_edge_type  = (const int*)  d_in[3];
    const float* diag_emb     = (const float*)d_in[4];
    const float* pro_emb      = (const float*)d_in[5];
    const float* W1           = (const float*)d_in[6];
    const float* root1        = (const float*)d_in[7];
    const float* b1           = (const float*)d_in[8];
    const float* W2           = (const float*)d_in[9];
    const float* root2        = (const float*)d_in[10];
    const float* b2           = (const float*)d_in[11];
    const float* gru_Wih      = (const float*)d_in[12];
    const float* gru_Whh      = (const float*)d_in[13];
    const float* gru_bih      = (const float*)d_in[14];
    const float* gru_bhh      = (const float*)d_in[15];
    const float* Wo1          = (const float*)d_in[16];
    const float* bo1          = (const float*)d_in[17];
    const float* Wo2          = (const float*)d_in[18];
    const float* bo2          = (const float*)d_in[19];
    float* out = (float*)d_out;

    void *p_cnt, *p_cread, *p_h, *p_wbig;
    cudaGetSymbolAddress(&p_cnt,   g_cnt);
    cudaGetSymbolAddress(&p_cread, g_cread);
    cudaGetSymbolAddress(&p_h,     g_h);
    cudaGetSymbolAddress(&p_wbig,  g_Wbig);
    float* wbig0 = (float*)p_wbig;

    // once per call: repack W1; build layer-1 dedup table (visit-independent)
    prep_wbig_kernel<<<(DIM * NCOLS + 255) / 256, 256>>>(W1, root1, wbig0);
    tabgemm_kernel<<<dim3(TAB_GRID_X, TAB_GRID_Y), 256>>>(diag_emb, pro_emb, wbig0, b1);
    cudaMemsetAsync(p_h, 0, DIM * sizeof(float));

    for (int t = 0; t < T_VISITS; t++) {
        const int* diag_t = c_diag_idx + (size_t)t * N_DIAG;
        const int* pro_t  = c_pro_idx  + (size_t)t * N_PRO;
        const int* src_t  = c_edge_index + (size_t)t * 2 * N_EDGES;
        const int* dst_t  = src_t + N_EDGES;
        const int* et_t   = c_edge_type + (size_t)t * N_EDGES;

        map_kernel<<<(N_NODES + 255) / 256, 256>>>(diag_t, pro_t);

        // ---- CSR build (shared by both layers) ----
        cudaMemsetAsync(p_cnt, 0, N_NODES * N_REL * sizeof(int));
        hist_kernel<<<(N_EDGES + 255) / 256, 256>>>(dst_t, et_t);
        scan_kernel<<<1, SCAN_T>>>();
        scatter_kernel<<<(N_EDGES + 255) / 256, 256>>>(src_t, dst_t, et_t);
        cudaMemsetAsync(p_cread, 0, DIM * sizeof(float));

        // ---- layer 1: dedup table + CSR gather (root+relu fused) ----
        gather_kernel<<<GATHER_BLOCKS, 256>>>();

        // ---- layer 2: aggregate-first + fused GEMM (bias+relu+readout) ----
        agg_kernel<<<GATHER_BLOCKS, 256>>>();
        gemm2_kernel<<<GEMM2_GRID, 256>>>(W2, root2, b2);

        gru_kernel<<<1, DIM>>>(gru_Wih, gru_Whh, gru_bih, gru_bhh);
    }
    out_kernel<<<1, 2 * DIM>>>(Wo1, bo1, Wo2, bo2, out);
}

// round 12
// speedup vs baseline: 1.4408x; 1.4408x over previous
#include <cuda_runtime.h>
#include <cuda_bf16.h>
#include <math.h>
#include <stdint.h>

#define DIM      128
#define N_DIAG   30000
#define N_PRO    20000
#define N_NODES  50000
#define N_EDGES  800000
#define N_REL    8
#define T_VISITS 2
#define NCOLS    (N_REL * DIM + DIM)   // 1152
#define NRD      (N_REL * DIM)         // 1024
#define VOC_DIAG 2000
#define VOC_PRO  1500
#define TAB_ROWS (VOC_DIAG + VOC_PRO)  // 3500
#define VOC3     150

// RULES LEARNED (hard way):
//  1. NO CUDA API calls before main().
//  2. NO register caps that cause spills (local-pool growth trips mem checkpoint).
//  3. From HOST code, pass device globals via cudaGetSymbolAddress, never by name.
//  4. R11 lesson: aggregate-first REGRESSED (+460us) — added 408MB DRAM round-trip
//     and GEMM wave imbalance. Transform-first + CSR gather is the right shape.
__device__ __align__(16) float g_x  [N_NODES * DIM];                 // layer output (relu'd)
__device__ __align__(16) float g_y  [N_NODES * DIM];                 // layer-2 root part
__device__ __align__(16) float g_xw [(size_t)N_NODES * NRD];         // layer-2 transforms
__device__ __align__(16) float g_tab[TAB_ROWS * NCOLS];              // layer-1 dedup table
__device__ __align__(16) int   g_map[N_NODES];                       // node -> table row
__device__ __align__(16) int   g_cnt[N_NODES * N_REL];               // (dst,rel) counts
__device__ __align__(16) int   g_off[N_NODES + 1];                   // CSR row offsets
__device__ __align__(16) int   g_pos[N_NODES];                       // scatter cursors
__device__ __align__(16) int   g_epk[N_EDGES];                       // packed src|et|map
__device__ __align__(16) int   g_blk[64];                            // scan block totals
__device__ __align__(16) int   g_blkoff[64];                         // scan block offsets
__device__ __align__(16) float g_Wbig[2][DIM * NCOLS];
__device__ __align__(16) float g_cread[DIM];
__device__ __align__(16) float g_h[DIM];

// ---------------- packed fp32 helpers (Blackwell FFMA2 via PTX f32x2) ----------------
__device__ __forceinline__ unsigned long long fma2(unsigned long long a,
                                                   unsigned long long b,
                                                   unsigned long long c)
{
    unsigned long long d;
    asm("fma.rn.f32x2 %0, %1, %2, %3;" : "=l"(d) : "l"(a), "l"(b), "l"(c));
    return d;
}
__device__ __forceinline__ float2 u2f(unsigned long long u)
{
    float2 f;
    asm("mov.b64 {%0, %1}, %2;" : "=f"(f.x), "=f"(f.y) : "l"(u));
    return f;
}

// ---------------- repack W: Wbig[d*1152 + c] = [W_r | root] ----------------
__global__ void prep_wbig_kernel(const float* __restrict__ W,
                                 const float* __restrict__ root,
                                 float* __restrict__ out)
{
    int idx = blockIdx.x * blockDim.x + threadIdx.x;
    if (idx >= DIM * NCOLS) return;
    int d = idx / NCOLS;
    int c = idx % NCOLS;
    float v;
    if (c < NRD) {
        int r = c >> 7, o = c & 127;
        v = W[(size_t)r * DIM * DIM + d * DIM + o];
    } else {
        v = root[d * DIM + (c - NRD)];
    }
    out[idx] = v;
}

// ---------------- node -> embedding-table row map ----------------
__global__ void map_kernel(const int* __restrict__ diag_idx,
                           const int* __restrict__ pro_idx)
{
    int n = blockIdx.x * blockDim.x + threadIdx.x;
    if (n >= N_NODES) return;
    int m;
    if (n < N_DIAG) m = min(max(diag_idx[n], 0), VOC_DIAG - 1);
    else            m = VOC_DIAG + min(max(pro_idx[n - N_DIAG], 0), VOC_PRO - 1);
    g_map[n] = m;
}

// ---------------- histogram of (dst, etype) ----------------
__global__ void hist_kernel(const int* __restrict__ dst, const int* __restrict__ et)
{
    int e = blockIdx.x * blockDim.x + threadIdx.x;
    if (e >= N_EDGES) return;
    int d = min(max(dst[e], 0), N_NODES - 1);
    int r = et[e] & (N_REL - 1);
    atomicAdd(&g_cnt[d * N_REL + r], 1);
}

// ---------------- 3-phase multi-block scan (replaces 1-block serial scan) ----------
#define SCAN_BLK 1024
#define SCAN_NBLK ((N_NODES + SCAN_BLK - 1) / SCAN_BLK)   // 49
__global__ __launch_bounds__(SCAN_BLK)
void scan_block_kernel()
{
    __shared__ int sdata[SCAN_BLK];
    int tid = threadIdx.x;
    int d = blockIdx.x * SCAN_BLK + tid;
    int v = 0;
    if (d < N_NODES) {
#pragma unroll
        for (int r = 0; r < N_REL; r++) v += g_cnt[d * N_REL + r];
    }
    sdata[tid] = v;
    __syncthreads();
    for (int ofs = 1; ofs < SCAN_BLK; ofs <<= 1) {
        int t = (tid >= ofs) ? sdata[tid - ofs] : 0;
        __syncthreads();
        sdata[tid] += t;
        __syncthreads();
    }
    if (d < N_NODES) g_off[d] = sdata[tid] - v;           // within-block exclusive
    if (tid == SCAN_BLK - 1) g_blk[blockIdx.x] = sdata[tid];
}
__global__ __launch_bounds__(64)
void scan_top_kernel()
{
    __shared__ int s[64];
    int tid = threadIdx.x;
    s[tid] = (tid < SCAN_NBLK) ? g_blk[tid] : 0;
    __syncthreads();
    for (int ofs = 1; ofs < 64; ofs <<= 1) {
        int t = (tid >= ofs) ? s[tid - ofs] : 0;
        __syncthreads();
        s[tid] += t;
        __syncthreads();
    }
    int v = (tid < SCAN_NBLK) ? g_blk[tid] : 0;
    if (tid < SCAN_NBLK) g_blkoff[tid] = s[tid] - v;      // exclusive
}
__global__ void scan_add_kernel()
{
    int d = blockIdx.x * blockDim.x + threadIdx.x;
    if (d >= N_NODES) return;
    int off = g_off[d] + g_blkoff[d >> 10];
    g_off[d] = off;
    g_pos[d] = off;
    if (d == 0) g_off[N_NODES] = N_EDGES;
}

// ---------------- scatter edges into CSR; pack src|et|map[src] ----------------
__global__ void scatter_kernel(const int* __restrict__ src, const int* __restrict__ dst,
                               const int* __restrict__ et)
{
    int e = blockIdx.x * blockDim.x + threadIdx.x;
    if (e >= N_EDGES) return;
    int d = min(max(__ldg(dst + e), 0), N_NODES - 1);
    int s = min(max(__ldg(src + e), 0), N_NODES - 1);
    int r = __ldg(et + e) & (N_REL - 1);
    int m = __ldg(&g_map[s]);
    int p = atomicAdd(&g_pos[d], 1);
    g_epk[p] = s | (r << 16) | (m << 19);
}

// ---------------- CSR gather: warp per dst, zero atomics, 8-deep MLP ----------------
#define GATHER_BLOCKS ((N_NODES + 7) / 8)
__global__ __launch_bounds__(256)
void gather_kernel(const float* __restrict__ XW, int row_stride, int layer1)
{
    int gw   = (blockIdx.x * 256 + threadIdx.x) >> 5;
    int lane = threadIdx.x & 31;
    if (gw >= N_NODES) return;
    const int d = gw;

    int b  = __ldg(&g_off[d]);
    int e2 = __ldg(&g_off[d + 1]);

    float nv = 0.f;
    if (lane < N_REL) {
        int c = __ldg(&g_cnt[d * N_REL + lane]);
        nv = 1.0f / (float)max(c, 1);
    }

    float4 acc = make_float4(0.f, 0.f, 0.f, 0.f);

#define GACC(pk) do {                                                        \
        int s_ = layer1 ? ((pk) >> 19) : ((pk) & 0xFFFF);                     \
        int r_ = ((pk) >> 16) & 7;                                           \
        float nm = __shfl_sync(0xFFFFFFFFu, nv, r_);                          \
        float4 v_ = *(const float4*)(XW + (size_t)s_ * row_stride             \
                                     + r_ * DIM + lane * 4);                  \
        acc.x += v_.x * nm; acc.y += v_.y * nm;                               \
        acc.z += v_.z * nm; acc.w += v_.w * nm;                               \
    } while (0)

    int i = b;
    for (; i + 8 <= e2; i += 8) {               // 8-deep MLP on the row reads
        int pk0 = __ldg(g_epk + i + 0);
        int pk1 = __ldg(g_epk + i + 1);
        int pk2 = __ldg(g_epk + i + 2);
        int pk3 = __ldg(g_epk + i + 3);
        int pk4 = __ldg(g_epk + i + 4);
        int pk5 = __ldg(g_epk + i + 5);
        int pk6 = __ldg(g_epk + i + 6);
        int pk7 = __ldg(g_epk + i + 7);
        GACC(pk0); GACC(pk1); GACC(pk2); GACC(pk3);
        GACC(pk4); GACC(pk5); GACC(pk6); GACC(pk7);
    }
    for (; i + 4 <= e2; i += 4) {
        int pk0 = __ldg(g_epk + i + 0);
        int pk1 = __ldg(g_epk + i + 1);
        int pk2 = __ldg(g_epk + i + 2);
        int pk3 = __ldg(g_epk + i + 3);
        GACC(pk0); GACC(pk1); GACC(pk2); GACC(pk3);
    }
    for (; i < e2; i++) { int pk = __ldg(g_epk + i); GACC(pk); }
#undef GACC

    float4 base;
    if (layer1) {
        int m = __ldg(&g_map[d]);
        base = *(const float4*)(g_tab + (size_t)m * NCOLS + NRD + lane * 4);
    } else {
        base = *(const float4*)(g_y + (size_t)d * DIM + lane * 4);
    }
    float4 o;
    o.x = fmaxf(base.x + acc.x, 0.f);
    o.y = fmaxf(base.y + acc.y, 0.f);
    o.z = fmaxf(base.z + acc.z, 0.f);
    o.w = fmaxf(base.w + acc.w, 0.f);
    *(float4*)(g_x + (size_t)d * DIM + lane * 4) = o;
}

// ======== table GEMM (3500 rows; small, plain-FMA form) ====
#define T_BM 128
#define T_BN 64
#define T_BK 32
#define TAB_GRID_X (NCOLS / T_BN)                      // 18
#define TAB_GRID_Y ((TAB_ROWS + T_BM - 1) / T_BM)      // 28
__global__ __launch_bounds__(256)
void tabgemm_kernel(const float* __restrict__ diag_emb,
                    const float* __restrict__ pro_emb,
                    const float* __restrict__ Bmat,
                    const float* __restrict__ bias)
{
    __shared__ float As[T_BK][T_BM + 4];
    __shared__ float Bs[T_BK][T_BN];

    const int block_m = blockIdx.y * T_BM;
    const int block_n = blockIdx.x * T_BN;
    const int tid = threadIdx.x;
    const int tx = tid & 15;
    const int ty = tid >> 4;

    float acc[8][4];
#pragma unroll
    for (int m = 0; m < 8; m++)
#pragma unroll
        for (int n = 0; n < 4; n++) acc[m][n] = 0.f;

    for (int kb = 0; kb < DIM; kb += T_BK) {
#pragma unroll
        for (int i = 0; i < 4; i++) {
            int fid = tid + i * 256;
            int r   = fid >> 3;
            int c   = (fid & 7) * 4;
            int row = block_m + r;
            float4 v = make_float4(0.f, 0.f, 0.f, 0.f);
            if (row < TAB_ROWS) {
                const float* srow = (row < VOC_DIAG)
                    ? diag_emb + (size_t)row * DIM
                    : pro_emb  + (size_t)(row - VOC_DIAG) * DIM;
                v = *(const float4*)(srow + kb + c);
            }
            As[c + 0][r] = v.x; As[c + 1][r] = v.y;
            As[c + 2][r] = v.z; As[c + 3][r] = v.w;
        }
#pragma unroll
        for (int i = 0; i < 2; i++) {
            int fid = tid + i * 256;
            int r   = fid >> 4;
            int c   = (fid & 15) * 4;
            *(float4*)(&Bs[r][c]) =
                *(const float4*)(Bmat + (size_t)(kb + r) * NCOLS + block_n + c);
        }
        __syncthreads();

#pragma unroll
        for (int k = 0; k < T_BK; k++) {
            float4 a0 = *(const float4*)(&As[k][ty * 8]);
            float4 a1 = *(const float4*)(&As[k][ty * 8 + 4]);
            float4 b  = *(const float4*)(&Bs[k][tx * 4]);
            float am[8] = {a0.x, a0.y, a0.z, a0.w, a1.x, a1.y, a1.z, a1.w};
#pragma unroll
            for (int m = 0; m < 8; m++) {
                acc[m][0] = fmaf(am[m], b.x, acc[m][0]);
                acc[m][1] = fmaf(am[m], b.y, acc[m][1]);
                acc[m][2] = fmaf(am[m], b.z, acc[m][2]);
                acc[m][3] = fmaf(am[m], b.w, acc[m][3]);
            }
        }
        __syncthreads();
    }

    const int col = block_n + tx * 4;
#pragma unroll
    for (int m = 0; m < 8; m++) {
        int row = block_m + ty * 8 + m;
        if (row >= TAB_ROWS) continue;
        float4 v = make_float4(acc[m][0], acc[m][1], acc[m][2], acc[m][3]);
        if (col >= NRD) {
            float4 bv = *(const float4*)(bias + (col - NRD));
            v.x += bv.x; v.y += bv.y; v.z += bv.z; v.w += bv.w;
        }
        *(float4*)(g_tab + (size_t)row * NCOLS + col) = v;
    }
}

// ======== layer-2 GEMM, FFMA2 edition (unchanged from R9/R10 — known good) ==========
#define BM 128
#define BN 128
#define BK 16
#define GEMM_GRID_X (NCOLS / BN)                       // 9
#define GEMM_GRID_Y ((N_NODES + BM - 1) / BM)          // 391
__global__ __launch_bounds__(256)
void gemm_kernel(const float* __restrict__ A, const float* __restrict__ B,
                 const float* __restrict__ bias)
{
    __shared__ float As2[BK][2 * BM + 8];
    __shared__ float Bs [BK][BN + 4];

    const int block_m = blockIdx.y * BM;
    const int block_n = blockIdx.x * BN;
    const int tid = threadIdx.x;
    const int tx = tid & 15;
    const int ty = tid >> 4;

    unsigned long long acc2[8][4];
#pragma unroll
    for (int m = 0; m < 8; m++)
#pragma unroll
        for (int n = 0; n < 4; n++) acc2[m][n] = 0ull;

    for (int kb = 0; kb < DIM; kb += BK) {
#pragma unroll
        for (int i = 0; i < 2; i++) {
            int fid = tid + i * 256;
            int r   = fid >> 2;
            int c   = (fid & 3) * 4;
            float4 v = make_float4(0.f, 0.f, 0.f, 0.f);
            if (block_m + r < N_NODES)
                v = *(const float4*)(A + (size_t)(block_m + r) * DIM + kb + c);
            *(float2*)(&As2[c + 0][2 * r]) = make_float2(v.x, v.x);
            *(float2*)(&As2[c + 1][2 * r]) = make_float2(v.y, v.y);
            *(float2*)(&As2[c + 2][2 * r]) = make_float2(v.z, v.z);
            *(float2*)(&As2[c + 3][2 * r]) = make_float2(v.w, v.w);
        }
#pragma unroll
        for (int i = 0; i < 2; i++) {
            int fid = tid + i * 256;
            int r   = fid >> 5;
            int c   = (fid & 31) * 4;
            *(float4*)(&Bs[r][c]) =
                *(const float4*)(B + (size_t)(kb + r) * NCOLS + block_n + c);
        }
        __syncthreads();

#pragma unroll
        for (int k = 0; k < BK; k++) {
            const ulonglong2* ap = (const ulonglong2*)(&As2[k][ty * 16]);
            ulonglong2 a01 = ap[0], a23 = ap[1], a45 = ap[2], a67 = ap[3];
            const ulonglong2* bp = (const ulonglong2*)(&Bs[k][tx * 8]);
            ulonglong2 bA = bp[0], bB = bp[1];
            unsigned long long am[8] = {a01.x, a01.y, a23.x, a23.y,
                                        a45.x, a45.y, a67.x, a67.y};
#pragma unroll
            for (int m = 0; m < 8; m++) {
                acc2[m][0] = fma2(am[m], bA.x, acc2[m][0]);
                acc2[m][1] = fma2(am[m], bA.y, acc2[m][1]);
                acc2[m][2] = fma2(am[m], bB.x, acc2[m][2]);
                acc2[m][3] = fma2(am[m], bB.y, acc2[m][3]);
            }
        }
        __syncthreads();
    }

    const int col0 = block_n + tx * 8;
#pragma unroll
    for (int m = 0; m < 8; m++) {
        int row = block_m + ty * 8 + m;
        if (row >= N_NODES) continue;
        float2 p0 = u2f(acc2[m][0]), p1 = u2f(acc2[m][1]);
        float2 p2 = u2f(acc2[m][2]), p3 = u2f(acc2[m][3]);
        float4 lo = make_float4(p0.x, p0.y, p1.x, p1.y);
        float4 hi = make_float4(p2.x, p2.y, p3.x, p3.y);
        if (col0 < NRD) {
            float4* dst = (float4*)(g_xw + (size_t)row * NRD + col0);
            dst[0] = lo; dst[1] = hi;
        } else {
            int cc = col0 - NRD;
            float4 b0 = *(const float4*)(bias + cc);
            float4 b1 = *(const float4*)(bias + cc + 4);
            lo.x += b0.x; lo.y += b0.y; lo.z += b0.z; lo.w += b0.w;
            hi.x += b1.x; hi.y += b1.y; hi.z += b1.z; hi.w += b1.w;
            float4* dst = (float4*)(g_y + (size_t)row * DIM + cc);
            dst[0] = lo; dst[1] = hi;
        }
    }
}

// ---------------- readout: cread += column sums of g_x ----------------
#define RO_ROWS 32
#define RO_BLOCKS ((N_NODES + RO_ROWS - 1) / RO_ROWS)
__global__ void readout_kernel()
{
    int col  = threadIdx.x;              // 128
    int row0 = blockIdx.x * RO_ROWS;
    float sum = 0.f;
#pragma unroll 4
    for (int i = 0; i < RO_ROWS; i++) {
        int row = row0 + i;
        if (row >= N_NODES) break;
        sum += g_x[(size_t)row * DIM + col];
    }
    atomicAdd(&g_cread[col], sum);
}

// ---------------- GRU cell (single block, 128 threads) ----------------
__global__ void gru_kernel(const float* __restrict__ Wih, const float* __restrict__ Whh,
                           const float* __restrict__ bih, const float* __restrict__ bhh)
{
    __shared__ float c[DIM], hh[DIM];
    int tid = threadIdx.x;
    c[tid]  = g_cread[tid];
    hh[tid] = g_h[tid];
    __syncthreads();

    float gi[3], gh[3];
#pragma unroll
    for (int g = 0; g < 3; g++) {
        int row = g * DIM + tid;
        float si = bih[row], sh = bhh[row];
        const float* wi = Wih + (size_t)row * DIM;
        const float* wh = Whh + (size_t)row * DIM;
        for (int d = 0; d < DIM; d++) {
            si = fmaf(c[d],  wi[d], si);
            sh = fmaf(hh[d], wh[d], sh);
        }
        gi[g] = si; gh[g] = sh;
    }
    float r = 1.0f / (1.0f + expf(-(gi[0] + gh[0])));
    float z = 1.0f / (1.0f + expf(-(gi[1] + gh[1])));
    float n = tanhf(gi[2] + r * gh[2]);
    float hn = (1.0f - z) * n + z * hh[tid];
    __syncthreads();
    g_h[tid] = hn;
}

// ---------------- output head (single block, 256 threads) ----------------
__global__ void out_kernel(const float* __restrict__ Wo1, const float* __restrict__ bo1,
                           const float* __restrict__ Wo2, const float* __restrict__ bo2,
                           float* __restrict__ out)
{
    __shared__ float hs[DIM], tmp[2 * DIM];
    int tid = threadIdx.x;
    if (tid < DIM) hs[tid] = g_h[tid];
    __syncthreads();
    {
        float a = bo1[tid];
        const float* w = Wo1 + (size_t)tid * DIM;
        for (int d = 0; d < DIM; d++) a = fmaf(hs[d], w[d], a);
        tmp[tid] = fmaxf(a, 0.f);
    }
    __syncthreads();
    if (tid < VOC3) {
        float o = bo2[tid];
        const float* w = Wo2 + (size_t)tid * 2 * DIM;
        for (int j = 0; j < 2 * DIM; j++) o = fmaf(tmp[j], w[j], o);
        out[tid] = o;
    }
}

// =============================== host launcher ===============================
extern "C" void kernel_launch(void* const* d_in, const int* in_sizes, int n_in,
                              void* d_out, int out_size)
{
    const int*   c_diag_idx   = (const int*)  d_in[0];
    const int*   c_pro_idx    = (const int*)  d_in[1];
    const int*   c_edge_index = (const int*)  d_in[2];
    const int*   c_edge_type  = (const int*)  d_in[3];
    const float* diag_emb     = (const float*)d_in[4];
    const float* pro_emb      = (const float*)d_in[5];
    const float* W1           = (const float*)d_in[6];
    const float* root1        = (const float*)d_in[7];
    const float* b1           = (const float*)d_in[8];
    const float* W2           = (const float*)d_in[9];
    const float* root2        = (const float*)d_in[10];
    const float* b2           = (const float*)d_in[11];
    const float* gru_Wih      = (const float*)d_in[12];
    const float* gru_Whh      = (const float*)d_in[13];
    const float* gru_bih      = (const float*)d_in[14];
    const float* gru_bhh      = (const float*)d_in[15];
    const float* Wo1          = (const float*)d_in[16];
    const float* bo1          = (const float*)d_in[17];
    const float* Wo2          = (const float*)d_in[18];
    const float* bo2          = (const float*)d_in[19];
    float* out = (float*)d_out;

    void *p_x, *p_tab, *p_xw, *p_cnt, *p_cread, *p_h, *p_wbig;
    cudaGetSymbolAddress(&p_x,     g_x);
    cudaGetSymbolAddress(&p_tab,   g_tab);
    cudaGetSymbolAddress(&p_xw,    g_xw);
    cudaGetSymbolAddress(&p_cnt,   g_cnt);
    cudaGetSymbolAddress(&p_cread, g_cread);
    cudaGetSymbolAddress(&p_h,     g_h);
    cudaGetSymbolAddress(&p_wbig,  g_Wbig);
    const float* x_dev   = (const float*)p_x;
    const float* tab_dev = (const float*)p_tab;
    const float* xw_dev  = (const float*)p_xw;
    float* wbig0 = (float*)p_wbig;
    float* wbig1 = wbig0 + DIM * NCOLS;

    // once per call: repack weights; build layer-1 dedup table (visit-independent)
    {
        int n = DIM * NCOLS;
        prep_wbig_kernel<<<(n + 255) / 256, 256>>>(W1, root1, wbig0);
        prep_wbig_kernel<<<(n + 255) / 256, 256>>>(W2, root2, wbig1);
    }
    tabgemm_kernel<<<dim3(TAB_GRID_X, TAB_GRID_Y), 256>>>(diag_emb, pro_emb, wbig0, b1);
    cudaMemsetAsync(p_h, 0, DIM * sizeof(float));

    for (int t = 0; t < T_VISITS; t++) {
        const int* diag_t = c_diag_idx + (size_t)t * N_DIAG;
        const int* pro_t  = c_pro_idx  + (size_t)t * N_PRO;
        const int* src_t  = c_edge_index + (size_t)t * 2 * N_EDGES;
        const int* dst_t  = src_t + N_EDGES;
        const int* et_t   = c_edge_type + (size_t)t * N_EDGES;

        map_kernel<<<(N_NODES + 255) / 256, 256>>>(diag_t, pro_t);

        // ---- CSR build (shared by both layers) ----
        cudaMemsetAsync(p_cnt, 0, N_NODES * N_REL * sizeof(int));
        hist_kernel<<<(N_EDGES + 255) / 256, 256>>>(dst_t, et_t);
        scan_block_kernel<<<SCAN_NBLK, SCAN_BLK>>>();
        scan_top_kernel<<<1, 64>>>();
        scan_add_kernel<<<(N_NODES + 255) / 256, 256>>>();
        scatter_kernel<<<(N_EDGES + 255) / 256, 256>>>(src_t, dst_t, et_t);
        cudaMemsetAsync(p_cread, 0, DIM * sizeof(float));

        // ---- layer 1: dedup table + CSR gather (root+relu fused) ----
        gather_kernel<<<GATHER_BLOCKS, 256>>>(tab_dev, NCOLS, 1);

        // ---- layer 2: FFMA2 GEMM + CSR gather (root+relu fused) ----
        gemm_kernel<<<dim3(GEMM_GRID_X, GEMM_GRID_Y), 256>>>(x_dev, wbig1, b2);
        gather_kernel<<<GATHER_BLOCKS, 256>>>(xw_dev, NRD, 0);

        readout_kernel<<<RO_BLOCKS, DIM>>>();
        gru_kernel<<<1, DIM>>>(gru_Wih, gru_Whh, gru_bih, gru_bhh);
    }
    out_kernel<<<1, 2 * DIM>>>(Wo1, bo1, Wo2, bo2, out);
}

// round 14
// speedup vs baseline: 1.5150x; 1.0515x over previous
#include <cuda_runtime.h>
#include <cuda_bf16.h>
#include <math.h>
#include <stdint.h>

#define DIM      128
#define N_DIAG   30000
#define N_PRO    20000
#define N_NODES  50000
#define N_EDGES  800000
#define N_REL    8
#define T_VISITS 2
#define NCOLS    (N_REL * DIM + DIM)   // 1152
#define NRD      (N_REL * DIM)         // 1024
#define VOC_DIAG 2000
#define VOC_PRO  1500
#define TAB_ROWS (VOC_DIAG + VOC_PRO)  // 3500
#define VOC3     150

// RULES LEARNED (hard way):
//  1. NO CUDA API calls before main().
//  2. NO register caps that cause spills (local-pool growth trips mem checkpoint).
//  3. From HOST code, pass device globals via cudaGetSymbolAddress, never by name.
//  4. Aggregate-first REGRESSED (+460us): extra 408MB DRAM round-trip. Keep
//     transform-first + CSR gather.
//  5. Visits are data-independent -> two forked streams (validated in R13:
//     capture + checkpoint both clean; R13 failed ONLY on the layer-1 gather
//     being passed the wrong base pointer. Fixed this round: pass g_tab.)
__device__ __align__(16) float g_x  [2][N_NODES * DIM];
__device__ __align__(16) float g_y  [2][N_NODES * DIM];
__device__ __align__(16) float g_xw [2][(size_t)N_NODES * NRD];
__device__ __align__(16) float g_tab[TAB_ROWS * NCOLS];
__device__ __align__(16) int   g_map[2][N_NODES];
__device__ __align__(16) int   g_cnt[2][N_NODES * N_REL];
__device__ __align__(16) int   g_off[2][N_NODES + 1];
__device__ __align__(16) int   g_pos[2][N_NODES];
__device__ __align__(16) int   g_epk[2][N_EDGES];
__device__ __align__(16) int   g_blk[2][64];
__device__ __align__(16) int   g_blkoff[2][64];
__device__ __align__(16) float g_Wbig[2][DIM * NCOLS];
__device__ __align__(16) float g_cread[2][DIM];
__device__ __align__(16) float g_h[DIM];

// ---------------- packed fp32 helpers (Blackwell FFMA2 via PTX f32x2) ----------------
__device__ __forceinline__ unsigned long long fma2(unsigned long long a,
                                                   unsigned long long b,
                                                   unsigned long long c)
{
    unsigned long long d;
    asm("fma.rn.f32x2 %0, %1, %2, %3;" : "=l"(d) : "l"(a), "l"(b), "l"(c));
    return d;
}
__device__ __forceinline__ float2 u2f(unsigned long long u)
{
    float2 f;
    asm("mov.b64 {%0, %1}, %2;" : "=f"(f.x), "=f"(f.y) : "l"(u));
    return f;
}

// ---------------- repack W: Wbig[d*1152 + c] = [W_r | root] ----------------
__global__ void prep_wbig_kernel(const float* __restrict__ W,
                                 const float* __restrict__ root,
                                 float* __restrict__ out)
{
    int idx = blockIdx.x * blockDim.x + threadIdx.x;
    if (idx >= DIM * NCOLS) return;
    int d = idx / NCOLS;
    int c = idx % NCOLS;
    float v;
    if (c < NRD) {
        int r = c >> 7, o = c & 127;
        v = W[(size_t)r * DIM * DIM + d * DIM + o];
    } else {
        v = root[d * DIM + (c - NRD)];
    }
    out[idx] = v;
}

// ---------------- node -> embedding-table row map ----------------
__global__ void map_kernel(const int* __restrict__ diag_idx,
                           const int* __restrict__ pro_idx,
                           int* __restrict__ map)
{
    int n = blockIdx.x * blockDim.x + threadIdx.x;
    if (n >= N_NODES) return;
    int m;
    if (n < N_DIAG) m = min(max(diag_idx[n], 0), VOC_DIAG - 1);
    else            m = VOC_DIAG + min(max(pro_idx[n - N_DIAG], 0), VOC_PRO - 1);
    map[n] = m;
}

// ---------------- histogram of (dst, etype) ----------------
__global__ void hist_kernel(const int* __restrict__ dst, const int* __restrict__ et,
                            int* __restrict__ cnt)
{
    int e = blockIdx.x * blockDim.x + threadIdx.x;
    if (e >= N_EDGES) return;
    int d = min(max(dst[e], 0), N_NODES - 1);
    int r = et[e] & (N_REL - 1);
    atomicAdd(&cnt[d * N_REL + r], 1);
}

// ---------------- 3-phase multi-block scan ----------------
#define SCAN_BLK 1024
#define SCAN_NBLK ((N_NODES + SCAN_BLK - 1) / SCAN_BLK)   // 49
__global__ __launch_bounds__(SCAN_BLK)
void scan_block_kernel(const int* __restrict__ cnt, int* __restrict__ off,
                       int* __restrict__ blk)
{
    __shared__ int sdata[SCAN_BLK];
    int tid = threadIdx.x;
    int d = blockIdx.x * SCAN_BLK + tid;
    int v = 0;
    if (d < N_NODES) {
#pragma unroll
        for (int r = 0; r < N_REL; r++) v += cnt[d * N_REL + r];
    }
    sdata[tid] = v;
    __syncthreads();
    for (int ofs = 1; ofs < SCAN_BLK; ofs <<= 1) {
        int t = (tid >= ofs) ? sdata[tid - ofs] : 0;
        __syncthreads();
        sdata[tid] += t;
        __syncthreads();
    }
    if (d < N_NODES) off[d] = sdata[tid] - v;
    if (tid == SCAN_BLK - 1) blk[blockIdx.x] = sdata[tid];
}
__global__ __launch_bounds__(64)
void scan_top_kernel(const int* __restrict__ blk, int* __restrict__ blkoff)
{
    __shared__ int s[64];
    int tid = threadIdx.x;
    s[tid] = (tid < SCAN_NBLK) ? blk[tid] : 0;
    __syncthreads();
    for (int ofs = 1; ofs < 64; ofs <<= 1) {
        int t = (tid >= ofs) ? s[tid - ofs] : 0;
        __syncthreads();
        s[tid] += t;
        __syncthreads();
    }
    int v = (tid < SCAN_NBLK) ? blk[tid] : 0;
    if (tid < SCAN_NBLK) blkoff[tid] = s[tid] - v;
}
__global__ void scan_add_kernel(int* __restrict__ off, int* __restrict__ pos,
                                const int* __restrict__ blkoff)
{
    int d = blockIdx.x * blockDim.x + threadIdx.x;
    if (d >= N_NODES) return;
    int o = off[d] + blkoff[d >> 10];
    off[d] = o;
    pos[d] = o;
    if (d == 0) off[N_NODES] = N_EDGES;
}

// ---------------- scatter edges into CSR; pack src|et|map[src] ----------------
__global__ void scatter_kernel(const int* __restrict__ src, const int* __restrict__ dst,
                               const int* __restrict__ et, const int* __restrict__ map,
                               int* __restrict__ pos, int* __restrict__ epk)
{
    int e = blockIdx.x * blockDim.x + threadIdx.x;
    if (e >= N_EDGES) return;
    int d = min(max(__ldg(dst + e), 0), N_NODES - 1);
    int s = min(max(__ldg(src + e), 0), N_NODES - 1);
    int r = __ldg(et + e) & (N_REL - 1);
    int m = __ldg(&map[s]);
    int p = atomicAdd(&pos[d], 1);
    epk[p] = s | (r << 16) | (m << 19);
}

// ---------------- CSR gather: warp per dst, zero atomics, 8-deep MLP ----------------
#define GATHER_BLOCKS ((N_NODES + 7) / 8)
__global__ __launch_bounds__(256)
void gather_kernel(const float* __restrict__ XW, int row_stride, int layer1,
                   const int* __restrict__ off, const int* __restrict__ cnt,
                   const int* __restrict__ epk, const int* __restrict__ map,
                   const float* __restrict__ ybase, float* __restrict__ xout)
{
    int gw   = (blockIdx.x * 256 + threadIdx.x) >> 5;
    int lane = threadIdx.x & 31;
    if (gw >= N_NODES) return;
    const int d = gw;

    int b  = __ldg(&off[d]);
    int e2 = __ldg(&off[d + 1]);

    float nv = 0.f;
    if (lane < N_REL) {
        int c = __ldg(&cnt[d * N_REL + lane]);
        nv = 1.0f / (float)max(c, 1);
    }

    float4 acc = make_float4(0.f, 0.f, 0.f, 0.f);

#define GACC(pk) do {                                                        \
        int s_ = layer1 ? ((pk) >> 19) : ((pk) & 0xFFFF);                     \
        int r_ = ((pk) >> 16) & 7;                                           \
        float nm = __shfl_sync(0xFFFFFFFFu, nv, r_);                          \
        float4 v_ = *(const float4*)(XW + (size_t)s_ * row_stride             \
                                     + r_ * DIM + lane * 4);                  \
        acc.x += v_.x * nm; acc.y += v_.y * nm;                               \
        acc.z += v_.z * nm; acc.w += v_.w * nm;                               \
    } while (0)

    int i = b;
    for (; i + 8 <= e2; i += 8) {
        int pk0 = __ldg(epk + i + 0);
        int pk1 = __ldg(epk + i + 1);
        int pk2 = __ldg(epk + i + 2);
        int pk3 = __ldg(epk + i + 3);
        int pk4 = __ldg(epk + i + 4);
        int pk5 = __ldg(epk + i + 5);
        int pk6 = __ldg(epk + i + 6);
        int pk7 = __ldg(epk + i + 7);
        GACC(pk0); GACC(pk1); GACC(pk2); GACC(pk3);
        GACC(pk4); GACC(pk5); GACC(pk6); GACC(pk7);
    }
    for (; i + 4 <= e2; i += 4) {
        int pk0 = __ldg(epk + i + 0);
        int pk1 = __ldg(epk + i + 1);
        int pk2 = __ldg(epk + i + 2);
        int pk3 = __ldg(epk + i + 3);
        GACC(pk0); GACC(pk1); GACC(pk2); GACC(pk3);
    }
    for (; i < e2; i++) { int pk = __ldg(epk + i); GACC(pk); }
#undef GACC

    float4 base;
    if (layer1) {
        int m = __ldg(&map[d]);
        base = *(const float4*)(g_tab + (size_t)m * NCOLS + NRD + lane * 4);
    } else {
        base = *(const float4*)(ybase + (size_t)d * DIM + lane * 4);
    }
    float4 o;
    o.x = fmaxf(base.x + acc.x, 0.f);
    o.y = fmaxf(base.y + acc.y, 0.f);
    o.z = fmaxf(base.z + acc.z, 0.f);
    o.w = fmaxf(base.w + acc.w, 0.f);
    *(float4*)(xout + (size_t)d * DIM + lane * 4) = o;
}

// ======== table GEMM (3500 rows; small, plain-FMA form) ====
#define T_BM 128
#define T_BN 64
#define T_BK 32
#define TAB_GRID_X (NCOLS / T_BN)                      // 18
#define TAB_GRID_Y ((TAB_ROWS + T_BM - 1) / T_BM)      // 28
__global__ __launch_bounds__(256)
void tabgemm_kernel(const float* __restrict__ diag_emb,
                    const float* __restrict__ pro_emb,
                    const float* __restrict__ Bmat,
                    const float* __restrict__ bias)
{
    __shared__ float As[T_BK][T_BM + 4];
    __shared__ float Bs[T_BK][T_BN];

    const int block_m = blockIdx.y * T_BM;
    const int block_n = blockIdx.x * T_BN;
    const int tid = threadIdx.x;
    const int tx = tid & 15;
    const int ty = tid >> 4;

    float acc[8][4];
#pragma unroll
    for (int m = 0; m < 8; m++)
#pragma unroll
        for (int n = 0; n < 4; n++) acc[m][n] = 0.f;

    for (int kb = 0; kb < DIM; kb += T_BK) {
#pragma unroll
        for (int i = 0; i < 4; i++) {
            int fid = tid + i * 256;
            int r   = fid >> 3;
            int c   = (fid & 7) * 4;
            int row = block_m + r;
            float4 v = make_float4(0.f, 0.f, 0.f, 0.f);
            if (row < TAB_ROWS) {
                const float* srow = (row < VOC_DIAG)
                    ? diag_emb + (size_t)row * DIM
                    : pro_emb  + (size_t)(row - VOC_DIAG) * DIM;
                v = *(const float4*)(srow + kb + c);
            }
            As[c + 0][r] = v.x; As[c + 1][r] = v.y;
            As[c + 2][r] = v.z; As[c + 3][r] = v.w;
        }
#pragma unroll
        for (int i = 0; i < 2; i++) {
            int fid = tid + i * 256;
            int r   = fid >> 4;
            int c   = (fid & 15) * 4;
            *(float4*)(&Bs[r][c]) =
                *(const float4*)(Bmat + (size_t)(kb + r) * NCOLS + block_n + c);
        }
        __syncthreads();

#pragma unroll
        for (int k = 0; k < T_BK; k++) {
            float4 a0 = *(const float4*)(&As[k][ty * 8]);
            float4 a1 = *(const float4*)(&As[k][ty * 8 + 4]);
            float4 b  = *(const float4*)(&Bs[k][tx * 4]);
            float am[8] = {a0.x, a0.y, a0.z, a0.w, a1.x, a1.y, a1.z, a1.w};
#pragma unroll
            for (int m = 0; m < 8; m++) {
                acc[m][0] = fmaf(am[m], b.x, acc[m][0]);
                acc[m][1] = fmaf(am[m], b.y, acc[m][1]);
                acc[m][2] = fmaf(am[m], b.z, acc[m][2]);
                acc[m][3] = fmaf(am[m], b.w, acc[m][3]);
            }
        }
        __syncthreads();
    }

    const int col = block_n + tx * 4;
#pragma unroll
    for (int m = 0; m < 8; m++) {
        int row = block_m + ty * 8 + m;
        if (row >= TAB_ROWS) continue;
        float4 v = make_float4(acc[m][0], acc[m][1], acc[m][2], acc[m][3]);
        if (col >= NRD) {
            float4 bv = *(const float4*)(bias + (col - NRD));
            v.x += bv.x; v.y += bv.y; v.z += bv.z; v.w += bv.w;
        }
        *(float4*)(g_tab + (size_t)row * NCOLS + col) = v;
    }
}

// ======== layer-2 GEMM, FFMA2 edition (body unchanged — known good) ==========
#define BM 128
#define BN 128
#define BK 16
#define GEMM_GRID_X (NCOLS / BN)                       // 9
#define GEMM_GRID_Y ((N_NODES + BM - 1) / BM)          // 391
__global__ __launch_bounds__(256)
void gemm_kernel(const float* __restrict__ A, const float* __restrict__ B,
                 const float* __restrict__ bias,
                 float* __restrict__ xw_out, float* __restrict__ y_out)
{
    __shared__ float As2[BK][2 * BM + 8];
    __shared__ float Bs [BK][BN + 4];

    const int block_m = blockIdx.y * BM;
    const int block_n = blockIdx.x * BN;
    const int tid = threadIdx.x;
    const int tx = tid & 15;
    const int ty = tid >> 4;

    unsigned long long acc2[8][4];
#pragma unroll
    for (int m = 0; m < 8; m++)
#pragma unroll
        for (int n = 0; n < 4; n++) acc2[m][n] = 0ull;

    for (int kb = 0; kb < DIM; kb += BK) {
#pragma unroll
        for (int i = 0; i < 2; i++) {
            int fid = tid + i * 256;
            int r   = fid >> 2;
            int c   = (fid & 3) * 4;
            float4 v = make_float4(0.f, 0.f, 0.f, 0.f);
            if (block_m + r < N_NODES)
                v = *(const float4*)(A + (size_t)(block_m + r) * DIM + kb + c);
            *(float2*)(&As2[c + 0][2 * r]) = make_float2(v.x, v.x);
            *(float2*)(&As2[c + 1][2 * r]) = make_float2(v.y, v.y);
            *(float2*)(&As2[c + 2][2 * r]) = make_float2(v.z, v.z);
            *(float2*)(&As2[c + 3][2 * r]) = make_float2(v.w, v.w);
        }
#pragma unroll
        for (int i = 0; i < 2; i++) {
            int fid = tid + i * 256;
            int r   = fid >> 5;
            int c   = (fid & 31) * 4;
            *(float4*)(&Bs[r][c]) =
                *(const float4*)(B + (size_t)(kb + r) * NCOLS + block_n + c);
        }
        __syncthreads();

#pragma unroll
        for (int k = 0; k < BK; k++) {
            const ulonglong2* ap = (const ulonglong2*)(&As2[k][ty * 16]);
            ulonglong2 a01 = ap[0], a23 = ap[1], a45 = ap[2], a67 = ap[3];
            const ulonglong2* bp = (const ulonglong2*)(&Bs[k][tx * 8]);
            ulonglong2 bA = bp[0], bB = bp[1];
            unsigned long long am[8] = {a01.x, a01.y, a23.x, a23.y,
                                        a45.x, a45.y, a67.x, a67.y};
#pragma unroll
            for (int m = 0; m < 8; m++) {
                acc2[m][0] = fma2(am[m], bA.x, acc2[m][0]);
                acc2[m][1] = fma2(am[m], bA.y, acc2[m][1]);
                acc2[m][2] = fma2(am[m], bB.x, acc2[m][2]);
                acc2[m][3] = fma2(am[m], bB.y, acc2[m][3]);
            }
        }
        __syncthreads();
    }

    const int col0 = block_n + tx * 8;
#pragma unroll
    for (int m = 0; m < 8; m++) {
        int row = block_m + ty * 8 + m;
        if (row >= N_NODES) continue;
        float2 p0 = u2f(acc2[m][0]), p1 = u2f(acc2[m][1]);
        float2 p2 = u2f(acc2[m][2]), p3 = u2f(acc2[m][3]);
        float4 lo = make_float4(p0.x, p0.y, p1.x, p1.y);
        float4 hi = make_float4(p2.x, p2.y, p3.x, p3.y);
        if (col0 < NRD) {
            float4* dst = (float4*)(xw_out + (size_t)row * NRD + col0);
            dst[0] = lo; dst[1] = hi;
        } else {
            int cc = col0 - NRD;
            float4 b0 = *(const float4*)(bias + cc);
            float4 b1 = *(const float4*)(bias + cc + 4);
            lo.x += b0.x; lo.y += b0.y; lo.z += b0.z; lo.w += b0.w;
            hi.x += b1.x; hi.y += b1.y; hi.z += b1.z; hi.w += b1.w;
            float4* dst = (float4*)(y_out + (size_t)row * DIM + cc);
            dst[0] = lo; dst[1] = hi;
        }
    }
}

// ---------------- readout: cread += column sums of x ----------------
#define RO_ROWS 32
#define RO_BLOCKS ((N_NODES + RO_ROWS - 1) / RO_ROWS)
__global__ void readout_kernel(const float* __restrict__ x, float* __restrict__ cread)
{
    int col  = threadIdx.x;              // 128
    int row0 = blockIdx.x * RO_ROWS;
    float sum = 0.f;
#pragma unroll 4
    for (int i = 0; i < RO_ROWS; i++) {
        int row = row0 + i;
        if (row >= N_NODES) break;
        sum += x[(size_t)row * DIM + col];
    }
    atomicAdd(&cread[col], sum);
}

// ---------------- GRU cell (single block, 128 threads) ----------------
__global__ void gru_kernel(const float* __restrict__ cread,
                           const float* __restrict__ Wih, const float* __restrict__ Whh,
                           const float* __restrict__ bih, const float* __restrict__ bhh)
{
    __shared__ float c[DIM], hh[DIM];
    int tid = threadIdx.x;
    c[tid]  = cread[tid];
    hh[tid] = g_h[tid];
    __syncthreads();

    float gi[3], gh[3];
#pragma unroll
    for (int g = 0; g < 3; g++) {
        int row = g * DIM + tid;
        float si = bih[row], sh = bhh[row];
        const float* wi = Wih + (size_t)row * DIM;
        const float* wh = Whh + (size_t)row * DIM;
        for (int d = 0; d < DIM; d++) {
            si = fmaf(c[d],  wi[d], si);
            sh = fmaf(hh[d], wh[d], sh);
        }
        gi[g] = si; gh[g] = sh;
    }
    float r = 1.0f / (1.0f + expf(-(gi[0] + gh[0])));
    float z = 1.0f / (1.0f + expf(-(gi[1] + gh[1])));
    float n = tanhf(gi[2] + r * gh[2]);
    float hn = (1.0f - z) * n + z * hh[tid];
    __syncthreads();
    g_h[tid] = hn;
}

// ---------------- output head (single block, 256 threads) ----------------
__global__ void out_kernel(const float* __restrict__ Wo1, const float* __restrict__ bo1,
                           const float* __restrict__ Wo2, const float* __restrict__ bo2,
                           float* __restrict__ out)
{
    __shared__ float hs[DIM], tmp[2 * DIM];
    int tid = threadIdx.x;
    if (tid < DIM) hs[tid] = g_h[tid];
    __syncthreads();
    {
        float a = bo1[tid];
        const float* w = Wo1 + (size_t)tid * DIM;
        for (int d = 0; d < DIM; d++) a = fmaf(hs[d], w[d], a);
        tmp[tid] = fmaxf(a, 0.f);
    }
    __syncthreads();
    if (tid < VOC3) {
        float o = bo2[tid];
        const float* w = Wo2 + (size_t)tid * 2 * DIM;
        for (int j = 0; j < 2 * DIM; j++) o = fmaf(tmp[j], w[j], o);
        out[tid] = o;
    }
}

// =============================== host launcher ===============================
extern "C" void kernel_launch(void* const* d_in, const int* in_sizes, int n_in,
                              void* d_out, int out_size)
{
    const int*   c_diag_idx   = (const int*)  d_in[0];
    const int*   c_pro_idx    = (const int*)  d_in[1];
    const int*   c_edge_index = (const int*)  d_in[2];
    const int*   c_edge_type  = (const int*)  d_in[3];
    const float* diag_emb     = (const float*)d_in[4];
    const float* pro_emb      = (const float*)d_in[5];
    const float* W1           = (const float*)d_in[6];
    const float* root1        = (const float*)d_in[7];
    const float* b1           = (const float*)d_in[8];
    const float* W2           = (const float*)d_in[9];
    const float* root2        = (const float*)d_in[10];
    const float* b2           = (const float*)d_in[11];
    const float* gru_Wih      = (const float*)d_in[12];
    const float* gru_Whh      = (const float*)d_in[13];
    const float* gru_bih      = (const float*)d_in[14];
    const float* gru_bhh      = (const float*)d_in[15];
    const float* Wo1          = (const float*)d_in[16];
    const float* bo1          = (const float*)d_in[17];
    const float* Wo2          = (const float*)d_in[18];
    const float* bo2          = (const float*)d_in[19];
    float* out = (float*)d_out;

    void *p_x, *p_y, *p_xw, *p_tab, *p_map, *p_cnt, *p_off, *p_pos, *p_epk;
    void *p_blk, *p_blkoff, *p_cread, *p_h, *p_wbig;
    cudaGetSymbolAddress(&p_x,      g_x);
    cudaGetSymbolAddress(&p_y,      g_y);
    cudaGetSymbolAddress(&p_xw,     g_xw);
    cudaGetSymbolAddress(&p_tab,    g_tab);     // R13 bug: layer-1 gather got p_x
    cudaGetSymbolAddress(&p_map,    g_map);     //          instead of p_tab -> 0.63
    cudaGetSymbolAddress(&p_cnt,    g_cnt);     //          rel_err. Fixed below.
    cudaGetSymbolAddress(&p_off,    g_off);
    cudaGetSymbolAddress(&p_pos,    g_pos);
    cudaGetSymbolAddress(&p_epk,    g_epk);
    cudaGetSymbolAddress(&p_blk,    g_blk);
    cudaGetSymbolAddress(&p_blkoff, g_blkoff);
    cudaGetSymbolAddress(&p_cread,  g_cread);
    cudaGetSymbolAddress(&p_h,      g_h);
    cudaGetSymbolAddress(&p_wbig,   g_Wbig);

    float* wbig0 = (float*)p_wbig;
    float* wbig1 = wbig0 + DIM * NCOLS;

    // fork/join resources: created per call, intentionally NOT destroyed
    // (destroying a stream/event participating in an active capture aborts it;
    // kernel_launch runs only ~2-3 times total, so the leak is bounded).
    cudaStream_t s2;
    cudaStreamCreate(&s2);
    cudaEvent_t ev_fork, ev_join;
    cudaEventCreateWithFlags(&ev_fork, cudaEventDisableTiming);
    cudaEventCreateWithFlags(&ev_join, cudaEventDisableTiming);

    // ---- shared prologue on the capture (legacy) stream ----
    {
        int n = DIM * NCOLS;
        prep_wbig_kernel<<<(n + 255) / 256, 256>>>(W1, root1, wbig0);
        prep_wbig_kernel<<<(n + 255) / 256, 256>>>(W2, root2, wbig1);
    }
    tabgemm_kernel<<<dim3(TAB_GRID_X, TAB_GRID_Y), 256>>>(diag_emb, pro_emb, wbig0, b1);
    cudaMemsetAsync(p_h, 0, DIM * sizeof(float));

    // fork: s2 joins the capture, ordered after tab/wbig
    cudaEventRecord(ev_fork, 0);
    cudaStreamWaitEvent(s2, ev_fork, 0);

    // ---- per-visit pipelines: visit 0 on legacy stream, visit 1 on s2 ----
    for (int t = 0; t < T_VISITS; t++) {
        cudaStream_t st = (t == 0) ? (cudaStream_t)0 : s2;
        const int* diag_t = c_diag_idx + (size_t)t * N_DIAG;
        const int* pro_t  = c_pro_idx  + (size_t)t * N_PRO;
        const int* src_t  = c_edge_index + (size_t)t * 2 * N_EDGES;
        const int* dst_t  = src_t + N_EDGES;
        const int* et_t   = c_edge_type + (size_t)t * N_EDGES;

        float* x_t      = (float*)p_x  + (size_t)t * N_NODES * DIM;
        float* y_t      = (float*)p_y  + (size_t)t * N_NODES * DIM;
        float* xw_t     = (float*)p_xw + (size_t)t * N_NODES * NRD;
        int*   map_t    = (int*)p_map  + (size_t)t * N_NODES;
        int*   cnt_t    = (int*)p_cnt  + (size_t)t * N_NODES * N_REL;
        int*   off_t    = (int*)p_off  + (size_t)t * (N_NODES + 1);
        int*   pos_t    = (int*)p_pos  + (size_t)t * N_NODES;
        int*   epk_t    = (int*)p_epk  + (size_t)t * N_EDGES;
        int*   blk_t    = (int*)p_blk  + (size_t)t * 64;
        int*   blkoff_t = (int*)p_blkoff + (size_t)t * 64;
        float* cread_t  = (float*)p_cread + (size_t)t * DIM;

        map_kernel<<<(N_NODES + 255) / 256, 256, 0, st>>>(diag_t, pro_t, map_t);

        cudaMemsetAsync(cnt_t, 0, N_NODES * N_REL * sizeof(int), st);
        hist_kernel<<<(N_EDGES + 255) / 256, 256, 0, st>>>(dst_t, et_t, cnt_t);
        scan_block_kernel<<<SCAN_NBLK, SCAN_BLK, 0, st>>>(cnt_t, off_t, blk_t);
        scan_top_kernel<<<1, 64, 0, st>>>(blk_t, blkoff_t);
        scan_add_kernel<<<(N_NODES + 255) / 256, 256, 0, st>>>(off_t, pos_t, blkoff_t);
        scatter_kernel<<<(N_EDGES + 255) / 256, 256, 0, st>>>(src_t, dst_t, et_t,
                                                              map_t, pos_t, epk_t);
        cudaMemsetAsync(cread_t, 0, DIM * sizeof(float), st);

        // layer 1: dedup table + CSR gather (root+relu fused) — reads g_tab rows
        gather_kernel<<<GATHER_BLOCKS, 256, 0, st>>>(
            (const float*)p_tab, NCOLS, 1, off_t, cnt_t, epk_t, map_t, y_t, x_t);

        // layer 2: FFMA2 GEMM + CSR gather (root+relu fused)
        gemm_kernel<<<dim3(GEMM_GRID_X, GEMM_GRID_Y), 256, 0, st>>>(
            x_t, wbig1, b2, xw_t, y_t);
        gather_kernel<<<GATHER_BLOCKS, 256, 0, st>>>(
            xw_t, NRD, 0, off_t, cnt_t, epk_t, map_t, y_t, x_t);

        readout_kernel<<<RO_BLOCKS, DIM, 0, st>>>(x_t, cread_t);
    }

    // join: legacy stream waits for visit 1
    cudaEventRecord(ev_join, s2);
    cudaStreamWaitEvent(0, ev_join, 0);

    // sequential GRU chain + head on legacy stream
    gru_kernel<<<1, DIM>>>((const float*)p_cread,       gru_Wih, gru_Whh, gru_bih, gru_bhh);
    gru_kernel<<<1, DIM>>>((const float*)p_cread + DIM, gru_Wih, gru_Whh, gru_bih, gru_bhh);
    out_kernel<<<1, 2 * DIM>>>(Wo1, bo1, Wo2, bo2, out);
}

// round 15
// speedup vs baseline: 1.6108x; 1.0632x over previous
#include <cuda_runtime.h>
#include <cuda_bf16.h>
#include <math.h>
#include <stdint.h>

#define DIM      128
#define N_DIAG   30000
#define N_PRO    20000
#define N_NODES  50000
#define N_EDGES  800000
#define N_REL    8
#define T_VISITS 2
#define NCOLS    (N_REL * DIM + DIM)   // 1152
#define NRD      (N_REL * DIM)         // 1024
#define VOC_DIAG 2000
#define VOC_PRO  1500
#define TAB_ROWS (VOC_DIAG + VOC_PRO)  // 3500
#define VOC3     150

// RULES LEARNED (hard way):
//  1. NO CUDA API calls before main().
//  2. NO register caps that cause spills (local-pool growth trips mem checkpoint).
//  3. From HOST code, pass device globals via cudaGetSymbolAddress, never by name.
//  4. Aggregate-first REGRESSED (+460us). Transform-first + CSR gather is right.
//  5. Two-stream overlap only hides wave TAILS (full-width kernels serialize);
//     total time ~= sum of kernel durations -> reduce per-kernel work.
//  6. This round: xw stored bf16 (102MB -> L2-resident random reads; messages
//     average over 50k nodes so bf16 noise ~1e-5 at output); layer-2 x output
//     is dead code -> gather2 folds the readout sum directly, no x store.
__device__ __align__(16) float          g_x  [2][N_NODES * DIM];
__device__ __align__(16) float          g_y  [2][N_NODES * DIM];
__device__ __align__(16) __nv_bfloat16  g_xw [2][(size_t)N_NODES * NRD];
__device__ __align__(16) float          g_tab[TAB_ROWS * NCOLS];
__device__ __align__(16) int            g_map[2][N_NODES];
__device__ __align__(16) int            g_cnt[2][N_NODES * N_REL];
__device__ __align__(16) int            g_off[2][N_NODES + 1];
__device__ __align__(16) int            g_pos[2][N_NODES];
__device__ __align__(16) int            g_epk[2][N_EDGES];
__device__ __align__(16) int            g_blk[2][64];
__device__ __align__(16) int            g_blkoff[2][64];
__device__ __align__(16) float          g_Wbig[2][DIM * NCOLS];
__device__ __align__(16) float          g_cread[2][DIM];
__device__ __align__(16) float          g_h[DIM];

// ---------------- packed fp32 helpers (Blackwell FFMA2 via PTX f32x2) ----------------
__device__ __forceinline__ unsigned long long fma2(unsigned long long a,
                                                   unsigned long long b,
                                                   unsigned long long c)
{
    unsigned long long d;
    asm("fma.rn.f32x2 %0, %1, %2, %3;" : "=l"(d) : "l"(a), "l"(b), "l"(c));
    return d;
}
__device__ __forceinline__ float2 u2f(unsigned long long u)
{
    float2 f;
    asm("mov.b64 {%0, %1}, %2;" : "=f"(f.x), "=f"(f.y) : "l"(u));
    return f;
}

// ---------------- repack W: Wbig[d*1152 + c] = [W_r | root] ----------------
__global__ void prep_wbig_kernel(const float* __restrict__ W,
                                 const float* __restrict__ root,
                                 float* __restrict__ out)
{
    int idx = blockIdx.x * blockDim.x + threadIdx.x;
    if (idx >= DIM * NCOLS) return;
    int d = idx / NCOLS;
    int c = idx % NCOLS;
    float v;
    if (c < NRD) {
        int r = c >> 7, o = c & 127;
        v = W[(size_t)r * DIM * DIM + d * DIM + o];
    } else {
        v = root[d * DIM + (c - NRD)];
    }
    out[idx] = v;
}

// ---------------- node -> embedding-table row map ----------------
__global__ void map_kernel(const int* __restrict__ diag_idx,
                           const int* __restrict__ pro_idx,
                           int* __restrict__ map)
{
    int n = blockIdx.x * blockDim.x + threadIdx.x;
    if (n >= N_NODES) return;
    int m;
    if (n < N_DIAG) m = min(max(diag_idx[n], 0), VOC_DIAG - 1);
    else            m = VOC_DIAG + min(max(pro_idx[n - N_DIAG], 0), VOC_PRO - 1);
    map[n] = m;
}

// ---------------- histogram of (dst, etype) ----------------
__global__ void hist_kernel(const int* __restrict__ dst, const int* __restrict__ et,
                            int* __restrict__ cnt)
{
    int e = blockIdx.x * blockDim.x + threadIdx.x;
    if (e >= N_EDGES) return;
    int d = min(max(dst[e], 0), N_NODES - 1);
    int r = et[e] & (N_REL - 1);
    atomicAdd(&cnt[d * N_REL + r], 1);
}

// ---------------- 3-phase multi-block scan ----------------
#define SCAN_BLK 1024
#define SCAN_NBLK ((N_NODES + SCAN_BLK - 1) / SCAN_BLK)   // 49
__global__ __launch_bounds__(SCAN_BLK)
void scan_block_kernel(const int* __restrict__ cnt, int* __restrict__ off,
                       int* __restrict__ blk)
{
    __shared__ int sdata[SCAN_BLK];
    int tid = threadIdx.x;
    int d = blockIdx.x * SCAN_BLK + tid;
    int v = 0;
    if (d < N_NODES) {
#pragma unroll
        for (int r = 0; r < N_REL; r++) v += cnt[d * N_REL + r];
    }
    sdata[tid] = v;
    __syncthreads();
    for (int ofs = 1; ofs < SCAN_BLK; ofs <<= 1) {
        int t = (tid >= ofs) ? sdata[tid - ofs] : 0;
        __syncthreads();
        sdata[tid] += t;
        __syncthreads();
    }
    if (d < N_NODES) off[d] = sdata[tid] - v;
    if (tid == SCAN_BLK - 1) blk[blockIdx.x] = sdata[tid];
}
__global__ __launch_bounds__(64)
void scan_top_kernel(const int* __restrict__ blk, int* __restrict__ blkoff)
{
    __shared__ int s[64];
    int tid = threadIdx.x;
    s[tid] = (tid < SCAN_NBLK) ? blk[tid] : 0;
    __syncthreads();
    for (int ofs = 1; ofs < 64; ofs <<= 1) {
        int t = (tid >= ofs) ? s[tid - ofs] : 0;
        __syncthreads();
        s[tid] += t;
        __syncthreads();
    }
    int v = (tid < SCAN_NBLK) ? blk[tid] : 0;
    if (tid < SCAN_NBLK) blkoff[tid] = s[tid] - v;
}
__global__ void scan_add_kernel(int* __restrict__ off, int* __restrict__ pos,
                                const int* __restrict__ blkoff)
{
    int d = blockIdx.x * blockDim.x + threadIdx.x;
    if (d >= N_NODES) return;
    int o = off[d] + blkoff[d >> 10];
    off[d] = o;
    pos[d] = o;
    if (d == 0) off[N_NODES] = N_EDGES;
}

// ---------------- scatter edges into CSR; pack src|et|map[src] ----------------
__global__ void scatter_kernel(const int* __restrict__ src, const int* __restrict__ dst,
                               const int* __restrict__ et, const int* __restrict__ map,
                               int* __restrict__ pos, int* __restrict__ epk)
{
    int e = blockIdx.x * blockDim.x + threadIdx.x;
    if (e >= N_EDGES) return;
    int d = min(max(__ldg(dst + e), 0), N_NODES - 1);
    int s = min(max(__ldg(src + e), 0), N_NODES - 1);
    int r = __ldg(et + e) & (N_REL - 1);
    int m = __ldg(&map[s]);
    int p = atomicAdd(&pos[d], 1);
    epk[p] = s | (r << 16) | (m << 19);
}

// ---------------- layer-1 CSR gather: fp32 tab rows, writes x ----------------
#define GATHER_BLOCKS ((N_NODES + 7) / 8)     // 6250 exactly (50000/8)
__global__ __launch_bounds__(256)
void gather1_kernel(const float* __restrict__ TAB,
                    const int* __restrict__ off, const int* __restrict__ cnt,
                    const int* __restrict__ epk, const int* __restrict__ map,
                    float* __restrict__ xout)
{
    int gw   = (blockIdx.x * 256 + threadIdx.x) >> 5;
    int lane = threadIdx.x & 31;
    if (gw >= N_NODES) return;
    const int d = gw;

    int b  = __ldg(&off[d]);
    int e2 = __ldg(&off[d + 1]);

    float nv = 0.f;
    if (lane < N_REL) {
        int c = __ldg(&cnt[d * N_REL + lane]);
        nv = 1.0f / (float)max(c, 1);
    }

    float4 acc = make_float4(0.f, 0.f, 0.f, 0.f);

#define GACC(pk) do {                                                        \
        int s_ = (pk) >> 19;                                                  \
        int r_ = ((pk) >> 16) & 7;                                           \
        float nm = __shfl_sync(0xFFFFFFFFu, nv, r_);                          \
        float4 v_ = *(const float4*)(TAB + (size_t)s_ * NCOLS                 \
                                     + r_ * DIM + lane * 4);                  \
        acc.x += v_.x * nm; acc.y += v_.y * nm;                               \
        acc.z += v_.z * nm; acc.w += v_.w * nm;                               \
    } while (0)

    int i = b;
    for (; i + 8 <= e2; i += 8) {
        int pk0 = __ldg(epk + i + 0);
        int pk1 = __ldg(epk + i + 1);
        int pk2 = __ldg(epk + i + 2);
        int pk3 = __ldg(epk + i + 3);
        int pk4 = __ldg(epk + i + 4);
        int pk5 = __ldg(epk + i + 5);
        int pk6 = __ldg(epk + i + 6);
        int pk7 = __ldg(epk + i + 7);
        GACC(pk0); GACC(pk1); GACC(pk2); GACC(pk3);
        GACC(pk4); GACC(pk5); GACC(pk6); GACC(pk7);
    }
    for (; i + 4 <= e2; i += 4) {
        int pk0 = __ldg(epk + i + 0);
        int pk1 = __ldg(epk + i + 1);
        int pk2 = __ldg(epk + i + 2);
        int pk3 = __ldg(epk + i + 3);
        GACC(pk0); GACC(pk1); GACC(pk2); GACC(pk3);
    }
    for (; i < e2; i++) { int pk = __ldg(epk + i); GACC(pk); }
#undef GACC

    int m = __ldg(&map[d]);
    float4 base = *(const float4*)(TAB + (size_t)m * NCOLS + NRD + lane * 4);
    float4 o;
    o.x = fmaxf(base.x + acc.x, 0.f);
    o.y = fmaxf(base.y + acc.y, 0.f);
    o.z = fmaxf(base.z + acc.z, 0.f);
    o.w = fmaxf(base.w + acc.w, 0.f);
    *(float4*)(xout + (size_t)d * DIM + lane * 4) = o;
}

// ---------------- layer-2 CSR gather: bf16 xw rows, folds readout, no x store ----
__global__ __launch_bounds__(256)
void gather2_kernel(const __nv_bfloat16* __restrict__ XW,
                    const int* __restrict__ off, const int* __restrict__ cnt,
                    const int* __restrict__ epk,
                    const float* __restrict__ ybase, float* __restrict__ cread)
{
    __shared__ float scol[DIM];
    int tid  = threadIdx.x;
    if (tid < DIM) scol[tid] = 0.f;
    __syncthreads();

    int gw   = (blockIdx.x * 256 + tid) >> 5;       // always < N_NODES (6250*8=50000)
    int lane = tid & 31;
    const int d = gw;

    int b  = __ldg(&off[d]);
    int e2 = __ldg(&off[d + 1]);

    float nv = 0.f;
    if (lane < N_REL) {
        int c = __ldg(&cnt[d * N_REL + lane]);
        nv = 1.0f / (float)max(c, 1);
    }

    float4 acc = make_float4(0.f, 0.f, 0.f, 0.f);

#define GACC2(pk) do {                                                       \
        int s_ = (pk) & 0xFFFF;                                               \
        int r_ = ((pk) >> 16) & 7;                                           \
        float nm = __shfl_sync(0xFFFFFFFFu, nv, r_);                          \
        uint2 u_ = *(const uint2*)(XW + (size_t)s_ * NRD + r_ * DIM + lane*4);\
        float2 f0 = __bfloat1622float2(*(const __nv_bfloat162*)&u_.x);        \
        float2 f1 = __bfloat1622float2(*(const __nv_bfloat162*)&u_.y);        \
        acc.x += f0.x * nm; acc.y += f0.y * nm;                               \
        acc.z += f1.x * nm; acc.w += f1.y * nm;                               \
    } while (0)

    int i = b;
    for (; i + 8 <= e2; i += 8) {
        int pk0 = __ldg(epk + i + 0);
        int pk1 = __ldg(epk + i + 1);
        int pk2 = __ldg(epk + i + 2);
        int pk3 = __ldg(epk + i + 3);
        int pk4 = __ldg(epk + i + 4);
        int pk5 = __ldg(epk + i + 5);
        int pk6 = __ldg(epk + i + 6);
        int pk7 = __ldg(epk + i + 7);
        GACC2(pk0); GACC2(pk1); GACC2(pk2); GACC2(pk3);
        GACC2(pk4); GACC2(pk5); GACC2(pk6); GACC2(pk7);
    }
    for (; i + 4 <= e2; i += 4) {
        int pk0 = __ldg(epk + i + 0);
        int pk1 = __ldg(epk + i + 1);
        int pk2 = __ldg(epk + i + 2);
        int pk3 = __ldg(epk + i + 3);
        GACC2(pk0); GACC2(pk1); GACC2(pk2); GACC2(pk3);
    }
    for (; i < e2; i++) { int pk = __ldg(epk + i); GACC2(pk); }
#undef GACC2

    float4 base = *(const float4*)(ybase + (size_t)d * DIM + lane * 4);
    float ox = fmaxf(base.x + acc.x, 0.f);
    float oy = fmaxf(base.y + acc.y, 0.f);
    float oz = fmaxf(base.z + acc.z, 0.f);
    float ow = fmaxf(base.w + acc.w, 0.f);

    // fold readout: per-block column sums, one global atomic per column
    atomicAdd(&scol[lane * 4 + 0], ox);
    atomicAdd(&scol[lane * 4 + 1], oy);
    atomicAdd(&scol[lane * 4 + 2], oz);
    atomicAdd(&scol[lane * 4 + 3], ow);
    __syncthreads();
    if (tid < DIM) atomicAdd(&cread[tid], scol[tid]);
}

// ======== table GEMM (3500 rows; small, plain-FMA form) ====
#define T_BM 128
#define T_BN 64
#define T_BK 32
#define TAB_GRID_X (NCOLS / T_BN)                      // 18
#define TAB_GRID_Y ((TAB_ROWS + T_BM - 1) / T_BM)      // 28
__global__ __launch_bounds__(256)
void tabgemm_kernel(const float* __restrict__ diag_emb,
                    const float* __restrict__ pro_emb,
                    const float* __restrict__ Bmat,
                    const float* __restrict__ bias)
{
    __shared__ float As[T_BK][T_BM + 4];
    __shared__ float Bs[T_BK][T_BN];

    const int block_m = blockIdx.y * T_BM;
    const int block_n = blockIdx.x * T_BN;
    const int tid = threadIdx.x;
    const int tx = tid & 15;
    const int ty = tid >> 4;

    float acc[8][4];
#pragma unroll
    for (int m = 0; m < 8; m++)
#pragma unroll
        for (int n = 0; n < 4; n++) acc[m][n] = 0.f;

    for (int kb = 0; kb < DIM; kb += T_BK) {
#pragma unroll
        for (int i = 0; i < 4; i++) {
            int fid = tid + i * 256;
            int r   = fid >> 3;
            int c   = (fid & 7) * 4;
            int row = block_m + r;
            float4 v = make_float4(0.f, 0.f, 0.f, 0.f);
            if (row < TAB_ROWS) {
                const float* srow = (row < VOC_DIAG)
                    ? diag_emb + (size_t)row * DIM
                    : pro_emb  + (size_t)(row - VOC_DIAG) * DIM;
                v = *(const float4*)(srow + kb + c);
            }
            As[c + 0][r] = v.x; As[c + 1][r] = v.y;
            As[c + 2][r] = v.z; As[c + 3][r] = v.w;
        }
#pragma unroll
        for (int i = 0; i < 2; i++) {
            int fid = tid + i * 256;
            int r   = fid >> 4;
            int c   = (fid & 15) * 4;
            *(float4*)(&Bs[r][c]) =
                *(const float4*)(Bmat + (size_t)(kb + r) * NCOLS + block_n + c);
        }
        __syncthreads();

#pragma unroll
        for (int k = 0; k < T_BK; k++) {
            float4 a0 = *(const float4*)(&As[k][ty * 8]);
            float4 a1 = *(const float4*)(&As[k][ty * 8 + 4]);
            float4 b  = *(const float4*)(&Bs[k][tx * 4]);
            float am[8] = {a0.x, a0.y, a0.z, a0.w, a1.x, a1.y, a1.z, a1.w};
#pragma unroll
            for (int m = 0; m < 8; m++) {
                acc[m][0] = fmaf(am[m], b.x, acc[m][0]);
                acc[m][1] = fmaf(am[m], b.y, acc[m][1]);
                acc[m][2] = fmaf(am[m], b.z, acc[m][2]);
                acc[m][3] = fmaf(am[m], b.w, acc[m][3]);
            }
        }
        __syncthreads();
    }

    const int col = block_n + tx * 4;
#pragma unroll
    for (int m = 0; m < 8; m++) {
        int row = block_m + ty * 8 + m;
        if (row >= TAB_ROWS) continue;
        float4 v = make_float4(acc[m][0], acc[m][1], acc[m][2], acc[m][3]);
        if (col >= NRD) {
            float4 bv = *(const float4*)(bias + (col - NRD));
            v.x += bv.x; v.y += bv.y; v.z += bv.z; v.w += bv.w;
        }
        *(float4*)(g_tab + (size_t)row * NCOLS + col) = v;
    }
}

// ======== layer-2 GEMM, FFMA2, bf16 xw output ==========
#define BM 128
#define BN 128
#define BK 16
#define GEMM_GRID_X (NCOLS / BN)                       // 9
#define GEMM_GRID_Y ((N_NODES + BM - 1) / BM)          // 391
__global__ __launch_bounds__(256)
void gemm_kernel(const float* __restrict__ A, const float* __restrict__ B,
                 const float* __restrict__ bias,
                 __nv_bfloat16* __restrict__ xw_out, float* __restrict__ y_out)
{
    __shared__ float As2[BK][2 * BM + 8];
    __shared__ float Bs [BK][BN + 4];

    const int block_m = blockIdx.y * BM;
    const int block_n = blockIdx.x * BN;
    const int tid = threadIdx.x;
    const int tx = tid & 15;
    const int ty = tid >> 4;

    unsigned long long acc2[8][4];
#pragma unroll
    for (int m = 0; m < 8; m++)
#pragma unroll
        for (int n = 0; n < 4; n++) acc2[m][n] = 0ull;

    for (int kb = 0; kb < DIM; kb += BK) {
#pragma unroll
        for (int i = 0; i < 2; i++) {
            int fid = tid + i * 256;
            int r   = fid >> 2;
            int c   = (fid & 3) * 4;
            float4 v = make_float4(0.f, 0.f, 0.f, 0.f);
            if (block_m + r < N_NODES)
                v = *(const float4*)(A + (size_t)(block_m + r) * DIM + kb + c);
            *(float2*)(&As2[c + 0][2 * r]) = make_float2(v.x, v.x);
            *(float2*)(&As2[c + 1][2 * r]) = make_float2(v.y, v.y);
            *(float2*)(&As2[c + 2][2 * r]) = make_float2(v.z, v.z);
            *(float2*)(&As2[c + 3][2 * r]) = make_float2(v.w, v.w);
        }
#pragma unroll
        for (int i = 0; i < 2; i++) {
            int fid = tid + i * 256;
            int r   = fid >> 5;
            int c   = (fid & 31) * 4;
            *(float4*)(&Bs[r][c]) =
                *(const float4*)(B + (size_t)(kb + r) * NCOLS + block_n + c);
        }
        __syncthreads();

#pragma unroll
        for (int k = 0; k < BK; k++) {
            const ulonglong2* ap = (const ulonglong2*)(&As2[k][ty * 16]);
            ulonglong2 a01 = ap[0], a23 = ap[1], a45 = ap[2], a67 = ap[3];
            const ulonglong2* bp = (const ulonglong2*)(&Bs[k][tx * 8]);
            ulonglong2 bA = bp[0], bB = bp[1];
            unsigned long long am[8] = {a01.x, a01.y, a23.x, a23.y,
                                        a45.x, a45.y, a67.x, a67.y};
#pragma unroll
            for (int m = 0; m < 8; m++) {
                acc2[m][0] = fma2(am[m], bA.x, acc2[m][0]);
                acc2[m][1] = fma2(am[m], bA.y, acc2[m][1]);
                acc2[m][2] = fma2(am[m], bB.x, acc2[m][2]);
                acc2[m][3] = fma2(am[m], bB.y, acc2[m][3]);
            }
        }
        __syncthreads();
    }

    const int col0 = block_n + tx * 8;
#pragma unroll
    for (int m = 0; m < 8; m++) {
        int row = block_m + ty * 8 + m;
        if (row >= N_NODES) continue;
        float2 p0 = u2f(acc2[m][0]), p1 = u2f(acc2[m][1]);
        float2 p2 = u2f(acc2[m][2]), p3 = u2f(acc2[m][3]);
        if (col0 < NRD) {
            __nv_bfloat162 q0 = __floats2bfloat162_rn(p0.x, p0.y);
            __nv_bfloat162 q1 = __floats2bfloat162_rn(p1.x, p1.y);
            __nv_bfloat162 q2 = __floats2bfloat162_rn(p2.x, p2.y);
            __nv_bfloat162 q3 = __floats2bfloat162_rn(p3.x, p3.y);
            uint4 pk;
            pk.x = *(unsigned int*)&q0; pk.y = *(unsigned int*)&q1;
            pk.z = *(unsigned int*)&q2; pk.w = *(unsigned int*)&q3;
            *(uint4*)(xw_out + (size_t)row * NRD + col0) = pk;
        } else {
            int cc = col0 - NRD;
            float4 b0 = *(const float4*)(bias + cc);
            float4 b1 = *(const float4*)(bias + cc + 4);
            float4 lo = make_float4(p0.x + b0.x, p0.y + b0.y, p1.x + b0.z, p1.y + b0.w);
            float4 hi = make_float4(p2.x + b1.x, p2.y + b1.y, p3.x + b1.z, p3.y + b1.w);
            float4* dst = (float4*)(y_out + (size_t)row * DIM + cc);
            dst[0] = lo; dst[1] = hi;
        }
    }
}

// ---------------- GRU cell (single block, 128 threads) ----------------
__global__ void gru_kernel(const float* __restrict__ cread,
                           const float* __restrict__ Wih, const float* __restrict__ Whh,
                           const float* __restrict__ bih, const float* __restrict__ bhh)
{
    __shared__ float c[DIM], hh[DIM];
    int tid = threadIdx.x;
    c[tid]  = cread[tid];
    hh[tid] = g_h[tid];
    __syncthreads();

    float gi[3], gh[3];
#pragma unroll
    for (int g = 0; g < 3; g++) {
        int row = g * DIM + tid;
        float si = bih[row], sh = bhh[row];
        const float* wi = Wih + (size_t)row * DIM;
        const float* wh = Whh + (size_t)row * DIM;
        for (int d = 0; d < DIM; d++) {
            si = fmaf(c[d],  wi[d], si);
            sh = fmaf(hh[d], wh[d], sh);
        }
        gi[g] = si; gh[g] = sh;
    }
    float r = 1.0f / (1.0f + expf(-(gi[0] + gh[0])));
    float z = 1.0f / (1.0f + expf(-(gi[1] + gh[1])));
    float n = tanhf(gi[2] + r * gh[2]);
    float hn = (1.0f - z) * n + z * hh[tid];
    __syncthreads();
    g_h[tid] = hn;
}

// ---------------- output head (single block, 256 threads) ----------------
__global__ void out_kernel(const float* __restrict__ Wo1, const float* __restrict__ bo1,
                           const float* __restrict__ Wo2, const float* __restrict__ bo2,
                           float* __restrict__ out)
{
    __shared__ float hs[DIM], tmp[2 * DIM];
    int tid = threadIdx.x;
    if (tid < DIM) hs[tid] = g_h[tid];
    __syncthreads();
    {
        float a = bo1[tid];
        const float* w = Wo1 + (size_t)tid * DIM;
        for (int d = 0; d < DIM; d++) a = fmaf(hs[d], w[d], a);
        tmp[tid] = fmaxf(a, 0.f);
    }
    __syncthreads();
    if (tid < VOC3) {
        float o = bo2[tid];
        const float* w = Wo2 + (size_t)tid * 2 * DIM;
        for (int j = 0; j < 2 * DIM; j++) o = fmaf(tmp[j], w[j], o);
        out[tid] = o;
    }
}

// =============================== host launcher ===============================
extern "C" void kernel_launch(void* const* d_in, const int* in_sizes, int n_in,
                              void* d_out, int out_size)
{
    const int*   c_diag_idx   = (const int*)  d_in[0];
    const int*   c_pro_idx    = (const int*)  d_in[1];
    const int*   c_edge_index = (const int*)  d_in[2];
    const int*   c_edge_type  = (const int*)  d_in[3];
    const float* diag_emb     = (const float*)d_in[4];
    const float* pro_emb      = (const float*)d_in[5];
    const float* W1           = (const float*)d_in[6];
    const float* root1        = (const float*)d_in[7];
    const float* b1           = (const float*)d_in[8];
    const float* W2           = (const float*)d_in[9];
    const float* root2        = (const float*)d_in[10];
    const float* b2           = (const float*)d_in[11];
    const float* gru_Wih      = (const float*)d_in[12];
    const float* gru_Whh      = (const float*)d_in[13];
    const float* gru_bih      = (const float*)d_in[14];
    const float* gru_bhh      = (const float*)d_in[15];
    const float* Wo1          = (const float*)d_in[16];
    const float* bo1          = (const float*)d_in[17];
    const float* Wo2          = (const float*)d_in[18];
    const float* bo2          = (const float*)d_in[19];
    float* out = (float*)d_out;

    void *p_x, *p_y, *p_xw, *p_tab, *p_map, *p_cnt, *p_off, *p_pos, *p_epk;
    void *p_blk, *p_blkoff, *p_cread, *p_h, *p_wbig;
    cudaGetSymbolAddress(&p_x,      g_x);
    cudaGetSymbolAddress(&p_y,      g_y);
    cudaGetSymbolAddress(&p_xw,     g_xw);
    cudaGetSymbolAddress(&p_tab,    g_tab);
    cudaGetSymbolAddress(&p_map,    g_map);
    cudaGetSymbolAddress(&p_cnt,    g_cnt);
    cudaGetSymbolAddress(&p_off,    g_off);
    cudaGetSymbolAddress(&p_pos,    g_pos);
    cudaGetSymbolAddress(&p_epk,    g_epk);
    cudaGetSymbolAddress(&p_blk,    g_blk);
    cudaGetSymbolAddress(&p_blkoff, g_blkoff);
    cudaGetSymbolAddress(&p_cread,  g_cread);
    cudaGetSymbolAddress(&p_h,      g_h);
    cudaGetSymbolAddress(&p_wbig,   g_Wbig);

    float* wbig0 = (float*)p_wbig;
    float* wbig1 = wbig0 + DIM * NCOLS;

    // fork/join resources: created per call, intentionally NOT destroyed
    cudaStream_t s2;
    cudaStreamCreate(&s2);
    cudaEvent_t ev_fork, ev_join;
    cudaEventCreateWithFlags(&ev_fork, cudaEventDisableTiming);
    cudaEventCreateWithFlags(&ev_join, cudaEventDisableTiming);

    // ---- shared prologue on the capture (legacy) stream ----
    {
        int n = DIM * NCOLS;
        prep_wbig_kernel<<<(n + 255) / 256, 256>>>(W1, root1, wbig0);
        prep_wbig_kernel<<<(n + 255) / 256, 256>>>(W2, root2, wbig1);
    }
    tabgemm_kernel<<<dim3(TAB_GRID_X, TAB_GRID_Y), 256>>>(diag_emb, pro_emb, wbig0, b1);
    cudaMemsetAsync(p_h, 0, DIM * sizeof(float));

    // fork: s2 joins the capture, ordered after tab/wbig
    cudaEventRecord(ev_fork, 0);
    cudaStreamWaitEvent(s2, ev_fork, 0);

    // ---- per-visit pipelines: visit 0 on legacy stream, visit 1 on s2 ----
    for (int t = 0; t < T_VISITS; t++) {
        cudaStream_t st = (t == 0) ? (cudaStream_t)0 : s2;
        const int* diag_t = c_diag_idx + (size_t)t * N_DIAG;
        const int* pro_t  = c_pro_idx  + (size_t)t * N_PRO;
        const int* src_t  = c_edge_index + (size_t)t * 2 * N_EDGES;
        const int* dst_t  = src_t + N_EDGES;
        const int* et_t   = c_edge_type + (size_t)t * N_EDGES;

        float*          x_t      = (float*)p_x  + (size_t)t * N_NODES * DIM;
        float*          y_t      = (float*)p_y  + (size_t)t * N_NODES * DIM;
        __nv_bfloat16*  xw_t     = (__nv_bfloat16*)p_xw + (size_t)t * N_NODES * NRD;
        int*            map_t    = (int*)p_map  + (size_t)t * N_NODES;
        int*            cnt_t    = (int*)p_cnt  + (size_t)t * N_NODES * N_REL;
        int*            off_t    = (int*)p_off  + (size_t)t * (N_NODES + 1);
        int*            pos_t    = (int*)p_pos  + (size_t)t * N_NODES;
        int*            epk_t    = (int*)p_epk  + (size_t)t * N_EDGES;
        int*            blk_t    = (int*)p_blk  + (size_t)t * 64;
        int*            blkoff_t = (int*)p_blkoff + (size_t)t * 64;
        float*          cread_t  = (float*)p_cread + (size_t)t * DIM;

        map_kernel<<<(N_NODES + 255) / 256, 256, 0, st>>>(diag_t, pro_t, map_t);

        cudaMemsetAsync(cnt_t, 0, N_NODES * N_REL * sizeof(int), st);
        hist_kernel<<<(N_EDGES + 255) / 256, 256, 0, st>>>(dst_t, et_t, cnt_t);
        scan_block_kernel<<<SCAN_NBLK, SCAN_BLK, 0, st>>>(cnt_t, off_t, blk_t);
        scan_top_kernel<<<1, 64, 0, st>>>(blk_t, blkoff_t);
        scan_add_kernel<<<(N_NODES + 255) / 256, 256, 0, st>>>(off_t, pos_t, blkoff_t);
        scatter_kernel<<<(N_EDGES + 255) / 256, 256, 0, st>>>(src_t, dst_t, et_t,
                                                              map_t, pos_t, epk_t);
        cudaMemsetAsync(cread_t, 0, DIM * sizeof(float), st);

        // layer 1: dedup table + CSR gather (root+relu fused)
        gather1_kernel<<<GATHER_BLOCKS, 256, 0, st>>>(
            (const float*)p_tab, off_t, cnt_t, epk_t, map_t, x_t);

        // layer 2: FFMA2 GEMM (bf16 xw out) + CSR gather with fused readout
        gemm_kernel<<<dim3(GEMM_GRID_X, GEMM_GRID_Y), 256, 0, st>>>(
            x_t, wbig1, b2, xw_t, y_t);
        gather2_kernel<<<GATHER_BLOCKS, 256, 0, st>>>(
            xw_t, off_t, cnt_t, epk_t, y_t, cread_t);
    }

    // join: legacy stream waits for visit 1
    cudaEventRecord(ev_join, s2);
    cudaStreamWaitEvent(0, ev_join, 0);

    // sequential GRU chain + head on legacy stream
    gru_kernel<<<1, DIM>>>((const float*)p_cread,       gru_Wih, gru_Whh, gru_bih, gru_bhh);
    gru_kernel<<<1, DIM>>>((const float*)p_cread + DIM, gru_Wih, gru_Whh, gru_bih, gru_bhh);
    out_kernel<<<1, 2 * DIM>>>(Wo1, bo1, Wo2, bo2, out);
}

// round 16
// speedup vs baseline: 1.6168x; 1.0037x over previous
#include <cuda_runtime.h>
#include <cuda_bf16.h>
#include <math.h>
#include <stdint.h>

#define DIM      128
#define N_DIAG   30000
#define N_PRO    20000
#define N_NODES  50000
#define N_EDGES  800000
#define N_REL    8
#define T_VISITS 2
#define NCOLS    (N_REL * DIM + DIM)   // 1152
#define NRD      (N_REL * DIM)         // 1024
#define VOC_DIAG 2000
#define VOC_PRO  1500
#define TAB_ROWS (VOC_DIAG + VOC_PRO)  // 3500
#define VOC3     150

// RULES LEARNED (hard way):
//  1. NO CUDA API calls before main().
//  2. NO register caps that cause spills (local-pool growth trips mem checkpoint).
//  3. From HOST code, pass device globals via cudaGetSymbolAddress, never by name.
//  4. Aggregate-first REGRESSED (+460us). Transform-first + CSR gather is right.
//  5. Two-stream overlap only hides wave TAILS; reduce per-kernel work instead.
//  6. bf16 on the random-read message path is free precision-wise (averaged over
//     ~16 edges then 50k nodes) and halves L2 traffic — validated on xw in R15
//     (rel_err stayed 0.0). This round: same trick on the layer-1 table.
__device__ __align__(16) float          g_x  [2][N_NODES * DIM];
__device__ __align__(16) float          g_y  [2][N_NODES * DIM];
__device__ __align__(16) __nv_bfloat16  g_xw [2][(size_t)N_NODES * NRD];
__device__ __align__(16) __nv_bfloat16  g_tabm[TAB_ROWS * NRD];   // bf16 message table
__device__ __align__(16) float          g_tabr[TAB_ROWS * DIM];   // fp32 root+bias table
__device__ __align__(16) int            g_map[2][N_NODES];
__device__ __align__(16) int            g_cnt[2][N_NODES * N_REL];
__device__ __align__(16) int            g_off[2][N_NODES + 1];
__device__ __align__(16) int            g_pos[2][N_NODES];
__device__ __align__(16) int            g_epk[2][N_EDGES];
__device__ __align__(16) int            g_blk[2][64];
__device__ __align__(16) int            g_blkoff[2][64];
__device__ __align__(16) float          g_Wbig[2][DIM * NCOLS];
__device__ __align__(16) float          g_cread[2][DIM];
__device__ __align__(16) float          g_h[DIM];

// ---------------- packed fp32 helpers (Blackwell FFMA2 via PTX f32x2) ----------------
__device__ __forceinline__ unsigned long long fma2(unsigned long long a,
                                                   unsigned long long b,
                                                   unsigned long long c)
{
    unsigned long long d;
    asm("fma.rn.f32x2 %0, %1, %2, %3;" : "=l"(d) : "l"(a), "l"(b), "l"(c));
    return d;
}
__device__ __forceinline__ float2 u2f(unsigned long long u)
{
    float2 f;
    asm("mov.b64 {%0, %1}, %2;" : "=f"(f.x), "=f"(f.y) : "l"(u));
    return f;
}

// ---------------- repack W: Wbig[d*1152 + c] = [W_r | root] ----------------
__global__ void prep_wbig_kernel(const float* __restrict__ W,
                                 const float* __restrict__ root,
                                 float* __restrict__ out)
{
    int idx = blockIdx.x * blockDim.x + threadIdx.x;
    if (idx >= DIM * NCOLS) return;
    int d = idx / NCOLS;
    int c = idx % NCOLS;
    float v;
    if (c < NRD) {
        int r = c >> 7, o = c & 127;
        v = W[(size_t)r * DIM * DIM + d * DIM + o];
    } else {
        v = root[d * DIM + (c - NRD)];
    }
    out[idx] = v;
}

// ---------------- node -> embedding-table row map ----------------
__global__ void map_kernel(const int* __restrict__ diag_idx,
                           const int* __restrict__ pro_idx,
                           int* __restrict__ map)
{
    int n = blockIdx.x * blockDim.x + threadIdx.x;
    if (n >= N_NODES) return;
    int m;
    if (n < N_DIAG) m = min(max(diag_idx[n], 0), VOC_DIAG - 1);
    else            m = VOC_DIAG + min(max(pro_idx[n - N_DIAG], 0), VOC_PRO - 1);
    map[n] = m;
}

// ---------------- histogram of (dst, etype) ----------------
__global__ void hist_kernel(const int* __restrict__ dst, const int* __restrict__ et,
                            int* __restrict__ cnt)
{
    int e = blockIdx.x * blockDim.x + threadIdx.x;
    if (e >= N_EDGES) return;
    int d = min(max(dst[e], 0), N_NODES - 1);
    int r = et[e] & (N_REL - 1);
    atomicAdd(&cnt[d * N_REL + r], 1);
}

// ---------------- 3-phase multi-block scan ----------------
#define SCAN_BLK 1024
#define SCAN_NBLK ((N_NODES + SCAN_BLK - 1) / SCAN_BLK)   // 49
__global__ __launch_bounds__(SCAN_BLK)
void scan_block_kernel(const int* __restrict__ cnt, int* __restrict__ off,
                       int* __restrict__ blk)
{
    __shared__ int sdata[SCAN_BLK];
    int tid = threadIdx.x;
    int d = blockIdx.x * SCAN_BLK + tid;
    int v = 0;
    if (d < N_NODES) {
#pragma unroll
        for (int r = 0; r < N_REL; r++) v += cnt[d * N_REL + r];
    }
    sdata[tid] = v;
    __syncthreads();
    for (int ofs = 1; ofs < SCAN_BLK; ofs <<= 1) {
        int t = (tid >= ofs) ? sdata[tid - ofs] : 0;
        __syncthreads();
        sdata[tid] += t;
        __syncthreads();
    }
    if (d < N_NODES) off[d] = sdata[tid] - v;
    if (tid == SCAN_BLK - 1) blk[blockIdx.x] = sdata[tid];
}
__global__ __launch_bounds__(64)
void scan_top_kernel(const int* __restrict__ blk, int* __restrict__ blkoff)
{
    __shared__ int s[64];
    int tid = threadIdx.x;
    s[tid] = (tid < SCAN_NBLK) ? blk[tid] : 0;
    __syncthreads();
    for (int ofs = 1; ofs < 64; ofs <<= 1) {
        int t = (tid >= ofs) ? s[tid - ofs] : 0;
        __syncthreads();
        s[tid] += t;
        __syncthreads();
    }
    int v = (tid < SCAN_NBLK) ? blk[tid] : 0;
    if (tid < SCAN_NBLK) blkoff[tid] = s[tid] - v;
}
__global__ void scan_add_kernel(int* __restrict__ off, int* __restrict__ pos,
                                const int* __restrict__ blkoff)
{
    int d = blockIdx.x * blockDim.x + threadIdx.x;
    if (d >= N_NODES) return;
    int o = off[d] + blkoff[d >> 10];
    off[d] = o;
    pos[d] = o;
    if (d == 0) off[N_NODES] = N_EDGES;
}

// ---------------- scatter edges into CSR; pack src|et|map[src] ----------------
__global__ void scatter_kernel(const int* __restrict__ src, const int* __restrict__ dst,
                               const int* __restrict__ et, const int* __restrict__ map,
                               int* __restrict__ pos, int* __restrict__ epk)
{
    int e = blockIdx.x * blockDim.x + threadIdx.x;
    if (e >= N_EDGES) return;
    int d = min(max(__ldg(dst + e), 0), N_NODES - 1);
    int s = min(max(__ldg(src + e), 0), N_NODES - 1);
    int r = __ldg(et + e) & (N_REL - 1);
    int m = __ldg(&map[s]);
    int p = atomicAdd(&pos[d], 1);
    epk[p] = s | (r << 16) | (m << 19);
}

// ---------------- layer-1 CSR gather: bf16 tabm rows, fp32 tabr base, writes x ----
#define GATHER_BLOCKS ((N_NODES + 7) / 8)     // 6250 exactly (50000/8)
__global__ __launch_bounds__(256)
void gather1_kernel(const __nv_bfloat16* __restrict__ TABM,
                    const float* __restrict__ TABR,
                    const int* __restrict__ off, const int* __restrict__ cnt,
                    const int* __restrict__ epk, const int* __restrict__ map,
                    float* __restrict__ xout)
{
    int gw   = (blockIdx.x * 256 + threadIdx.x) >> 5;
    int lane = threadIdx.x & 31;
    const int d = gw;            // 6250*8 == 50000: no bounds check needed

    int b  = __ldg(&off[d]);
    int e2 = __ldg(&off[d + 1]);

    float nv = 0.f;
    if (lane < N_REL) {
        int c = __ldg(&cnt[d * N_REL + lane]);
        nv = 1.0f / (float)max(c, 1);
    }

    float4 acc = make_float4(0.f, 0.f, 0.f, 0.f);

#define GACC1(pk) do {                                                        \
        int s_ = (pk) >> 19;                                                   \
        int r_ = ((pk) >> 16) & 7;                                            \
        float nm = __shfl_sync(0xFFFFFFFFu, nv, r_);                           \
        uint2 u_ = *(const uint2*)(TABM + (size_t)s_ * NRD + r_ * DIM + lane*4);\
        float2 f0 = __bfloat1622float2(*(const __nv_bfloat162*)&u_.x);         \
        float2 f1 = __bfloat1622float2(*(const __nv_bfloat162*)&u_.y);         \
        acc.x += f0.x * nm; acc.y += f0.y * nm;                                \
        acc.z += f1.x * nm; acc.w += f1.y * nm;                                \
    } while (0)

    int i = b;
    for (; i + 8 <= e2; i += 8) {
        int pk0 = __ldg(epk + i + 0);
        int pk1 = __ldg(epk + i + 1);
        int pk2 = __ldg(epk + i + 2);
        int pk3 = __ldg(epk + i + 3);
        int pk4 = __ldg(epk + i + 4);
        int pk5 = __ldg(epk + i + 5);
        int pk6 = __ldg(epk + i + 6);
        int pk7 = __ldg(epk + i + 7);
        GACC1(pk0); GACC1(pk1); GACC1(pk2); GACC1(pk3);
        GACC1(pk4); GACC1(pk5); GACC1(pk6); GACC1(pk7);
    }
    for (; i + 4 <= e2; i += 4) {
        int pk0 = __ldg(epk + i + 0);
        int pk1 = __ldg(epk + i + 1);
        int pk2 = __ldg(epk + i + 2);
        int pk3 = __ldg(epk + i + 3);
        GACC1(pk0); GACC1(pk1); GACC1(pk2); GACC1(pk3);
    }
    for (; i < e2; i++) { int pk = __ldg(epk + i); GACC1(pk); }
#undef GACC1

    int m = __ldg(&map[d]);
    float4 base = *(const float4*)(TABR + (size_t)m * DIM + lane * 4);
    float4 o;
    o.x = fmaxf(base.x + acc.x, 0.f);
    o.y = fmaxf(base.y + acc.y, 0.f);
    o.z = fmaxf(base.z + acc.z, 0.f);
    o.w = fmaxf(base.w + acc.w, 0.f);
    *(float4*)(xout + (size_t)d * DIM + lane * 4) = o;
}

// ---------------- layer-2 CSR gather: bf16 xw rows, folds readout, no x store ----
__global__ __launch_bounds__(256)
void gather2_kernel(const __nv_bfloat16* __restrict__ XW,
                    const int* __restrict__ off, const int* __restrict__ cnt,
                    const int* __restrict__ epk,
                    const float* __restrict__ ybase, float* __restrict__ cread)
{
    __shared__ float scol[DIM];
    int tid  = threadIdx.x;
    if (tid < DIM) scol[tid] = 0.f;
    __syncthreads();

    int gw   = (blockIdx.x * 256 + tid) >> 5;
    int lane = tid & 31;
    const int d = gw;

    int b  = __ldg(&off[d]);
    int e2 = __ldg(&off[d + 1]);

    float nv = 0.f;
    if (lane < N_REL) {
        int c = __ldg(&cnt[d * N_REL + lane]);
        nv = 1.0f / (float)max(c, 1);
    }

    float4 acc = make_float4(0.f, 0.f, 0.f, 0.f);

#define GACC2(pk) do {                                                       \
        int s_ = (pk) & 0xFFFF;                                               \
        int r_ = ((pk) >> 16) & 7;                                           \
        float nm = __shfl_sync(0xFFFFFFFFu, nv, r_);                          \
        uint2 u_ = *(const uint2*)(XW + (size_t)s_ * NRD + r_ * DIM + lane*4);\
        float2 f0 = __bfloat1622float2(*(const __nv_bfloat162*)&u_.x);        \
        float2 f1 = __bfloat1622float2(*(const __nv_bfloat162*)&u_.y);        \
        acc.x += f0.x * nm; acc.y += f0.y * nm;                               \
        acc.z += f1.x * nm; acc.w += f1.y * nm;                               \
    } while (0)

    int i = b;
    for (; i + 8 <= e2; i += 8) {
        int pk0 = __ldg(epk + i + 0);
        int pk1 = __ldg(epk + i + 1);
        int pk2 = __ldg(epk + i + 2);
        int pk3 = __ldg(epk + i + 3);
        int pk4 = __ldg(epk + i + 4);
        int pk5 = __ldg(epk + i + 5);
        int pk6 = __ldg(epk + i + 6);
        int pk7 = __ldg(epk + i + 7);
        GACC2(pk0); GACC2(pk1); GACC2(pk2); GACC2(pk3);
        GACC2(pk4); GACC2(pk5); GACC2(pk6); GACC2(pk7);
    }
    for (; i + 4 <= e2; i += 4) {
        int pk0 = __ldg(epk + i + 0);
        int pk1 = __ldg(epk + i + 1);
        int pk2 = __ldg(epk + i + 2);
        int pk3 = __ldg(epk + i + 3);
        GACC2(pk0); GACC2(pk1); GACC2(pk2); GACC2(pk3);
    }
    for (; i < e2; i++) { int pk = __ldg(epk + i); GACC2(pk); }
#undef GACC2

    float4 base = *(const float4*)(ybase + (size_t)d * DIM + lane * 4);
    float ox = fmaxf(base.x + acc.x, 0.f);
    float oy = fmaxf(base.y + acc.y, 0.f);
    float oz = fmaxf(base.z + acc.z, 0.f);
    float ow = fmaxf(base.w + acc.w, 0.f);

    atomicAdd(&scol[lane * 4 + 0], ox);
    atomicAdd(&scol[lane * 4 + 1], oy);
    atomicAdd(&scol[lane * 4 + 2], oz);
    atomicAdd(&scol[lane * 4 + 3], ow);
    __syncthreads();
    if (tid < DIM) atomicAdd(&cread[tid], scol[tid]);
}

// ======== table GEMM: splits output into bf16 message table + fp32 root table ====
#define T_BM 128
#define T_BN 64
#define T_BK 32
#define TAB_GRID_X (NCOLS / T_BN)                      // 18
#define TAB_GRID_Y ((TAB_ROWS + T_BM - 1) / T_BM)      // 28
__global__ __launch_bounds__(256)
void tabgemm_kernel(const float* __restrict__ diag_emb,
                    const float* __restrict__ pro_emb,
                    const float* __restrict__ Bmat,
                    const float* __restrict__ bias)
{
    __shared__ float As[T_BK][T_BM + 4];
    __shared__ float Bs[T_BK][T_BN];

    const int block_m = blockIdx.y * T_BM;
    const int block_n = blockIdx.x * T_BN;
    const int tid = threadIdx.x;
    const int tx = tid & 15;
    const int ty = tid >> 4;

    float acc[8][4];
#pragma unroll
    for (int m = 0; m < 8; m++)
#pragma unroll
        for (int n = 0; n < 4; n++) acc[m][n] = 0.f;

    for (int kb = 0; kb < DIM; kb += T_BK) {
#pragma unroll
        for (int i = 0; i < 4; i++) {
            int fid = tid + i * 256;
            int r   = fid >> 3;
            int c   = (fid & 7) * 4;
            int row = block_m + r;
            float4 v = make_float4(0.f, 0.f, 0.f, 0.f);
            if (row < TAB_ROWS) {
                const float* srow = (row < VOC_DIAG)
                    ? diag_emb + (size_t)row * DIM
                    : pro_emb  + (size_t)(row - VOC_DIAG) * DIM;
                v = *(const float4*)(srow + kb + c);
            }
            As[c + 0][r] = v.x; As[c + 1][r] = v.y;
            As[c + 2][r] = v.z; As[c + 3][r] = v.w;
        }
#pragma unroll
        for (int i = 0; i < 2; i++) {
            int fid = tid + i * 256;
            int r   = fid >> 4;
            int c   = (fid & 15) * 4;
            *(float4*)(&Bs[r][c]) =
                *(const float4*)(Bmat + (size_t)(kb + r) * NCOLS + block_n + c);
        }
        __syncthreads();

#pragma unroll
        for (int k = 0; k < T_BK; k++) {
            float4 a0 = *(const float4*)(&As[k][ty * 8]);
            float4 a1 = *(const float4*)(&As[k][ty * 8 + 4]);
            float4 b  = *(const float4*)(&Bs[k][tx * 4]);
            float am[8] = {a0.x, a0.y, a0.z, a0.w, a1.x, a1.y, a1.z, a1.w};
#pragma unroll
            for (int m = 0; m < 8; m++) {
                acc[m][0] = fmaf(am[m], b.x, acc[m][0]);
                acc[m][1] = fmaf(am[m], b.y, acc[m][1]);
                acc[m][2] = fmaf(am[m], b.z, acc[m][2]);
                acc[m][3] = fmaf(am[m], b.w, acc[m][3]);
            }
        }
        __syncthreads();
    }

    const int col = block_n + tx * 4;
#pragma unroll
    for (int m = 0; m < 8; m++) {
        int row = block_m + ty * 8 + m;
        if (row >= TAB_ROWS) continue;
        if (col < NRD) {
            __nv_bfloat162 q0 = __floats2bfloat162_rn(acc[m][0], acc[m][1]);
            __nv_bfloat162 q1 = __floats2bfloat162_rn(acc[m][2], acc[m][3]);
            uint2 pk;
            pk.x = *(unsigned int*)&q0; pk.y = *(unsigned int*)&q1;
            *(uint2*)(g_tabm + (size_t)row * NRD + col) = pk;
        } else {
            int cc = col - NRD;
            float4 bv = *(const float4*)(bias + cc);
            float4 v = make_float4(acc[m][0] + bv.x, acc[m][1] + bv.y,
                                   acc[m][2] + bv.z, acc[m][3] + bv.w);
            *(float4*)(g_tabr + (size_t)row * DIM + cc) = v;
        }
    }
}

// ======== layer-2 GEMM, FFMA2, bf16 xw output (unchanged — known good) ==========
#define BM 128
#define BN 128
#define BK 16
#define GEMM_GRID_X (NCOLS / BN)                       // 9
#define GEMM_GRID_Y ((N_NODES + BM - 1) / BM)          // 391
__global__ __launch_bounds__(256)
void gemm_kernel(const float* __restrict__ A, const float* __restrict__ B,
                 const float* __restrict__ bias,
                 __nv_bfloat16* __restrict__ xw_out, float* __restrict__ y_out)
{
    __shared__ float As2[BK][2 * BM + 8];
    __shared__ float Bs [BK][BN + 4];

    const int block_m = blockIdx.y * BM;
    const int block_n = blockIdx.x * BN;
    const int tid = threadIdx.x;
    const int tx = tid & 15;
    const int ty = tid >> 4;

    unsigned long long acc2[8][4];
#pragma unroll
    for (int m = 0; m < 8; m++)
#pragma unroll
        for (int n = 0; n < 4; n++) acc2[m][n] = 0ull;

    for (int kb = 0; kb < DIM; kb += BK) {
#pragma unroll
        for (int i = 0; i < 2; i++) {
            int fid = tid + i * 256;
            int r   = fid >> 2;
            int c   = (fid & 3) * 4;
            float4 v = make_float4(0.f, 0.f, 0.f, 0.f);
            if (block_m + r < N_NODES)
                v = *(const float4*)(A + (size_t)(block_m + r) * DIM + kb + c);
            *(float2*)(&As2[c + 0][2 * r]) = make_float2(v.x, v.x);
            *(float2*)(&As2[c + 1][2 * r]) = make_float2(v.y, v.y);
            *(float2*)(&As2[c + 2][2 * r]) = make_float2(v.z, v.z);
            *(float2*)(&As2[c + 3][2 * r]) = make_float2(v.w, v.w);
        }
#pragma unroll
        for (int i = 0; i < 2; i++) {
            int fid = tid + i * 256;
            int r   = fid >> 5;
            int c   = (fid & 31) * 4;
            *(float4*)(&Bs[r][c]) =
                *(const float4*)(B + (size_t)(kb + r) * NCOLS + block_n + c);
        }
        __syncthreads();

#pragma unroll
        for (int k = 0; k < BK; k++) {
            const ulonglong2* ap = (const ulonglong2*)(&As2[k][ty * 16]);
            ulonglong2 a01 = ap[0], a23 = ap[1], a45 = ap[2], a67 = ap[3];
            const ulonglong2* bp = (const ulonglong2*)(&Bs[k][tx * 8]);
            ulonglong2 bA = bp[0], bB = bp[1];
            unsigned long long am[8] = {a01.x, a01.y, a23.x, a23.y,
                                        a45.x, a45.y, a67.x, a67.y};
#pragma unroll
            for (int m = 0; m < 8; m++) {
                acc2[m][0] = fma2(am[m], bA.x, acc2[m][0]);
                acc2[m][1] = fma2(am[m], bA.y, acc2[m][1]);
                acc2[m][2] = fma2(am[m], bB.x, acc2[m][2]);
                acc2[m][3] = fma2(am[m], bB.y, acc2[m][3]);
            }
        }
        __syncthreads();
    }

    const int col0 = block_n + tx * 8;
#pragma unroll
    for (int m = 0; m < 8; m++) {
        int row = block_m + ty * 8 + m;
        if (row >= N_NODES) continue;
        float2 p0 = u2f(acc2[m][0]), p1 = u2f(acc2[m][1]);
        float2 p2 = u2f(acc2[m][2]), p3 = u2f(acc2[m][3]);
        if (col0 < NRD) {
            __nv_bfloat162 q0 = __floats2bfloat162_rn(p0.x, p0.y);
            __nv_bfloat162 q1 = __floats2bfloat162_rn(p1.x, p1.y);
            __nv_bfloat162 q2 = __floats2bfloat162_rn(p2.x, p2.y);
            __nv_bfloat162 q3 = __floats2bfloat162_rn(p3.x, p3.y);
            uint4 pk;
            pk.x = *(unsigned int*)&q0; pk.y = *(unsigned int*)&q1;
            pk.z = *(unsigned int*)&q2; pk.w = *(unsigned int*)&q3;
            *(uint4*)(xw_out + (size_t)row * NRD + col0) = pk;
        } else {
            int cc = col0 - NRD;
            float4 b0 = *(const float4*)(bias + cc);
            float4 b1 = *(const float4*)(bias + cc + 4);
            float4 lo = make_float4(p0.x + b0.x, p0.y + b0.y, p1.x + b0.z, p1.y + b0.w);
            float4 hi = make_float4(p2.x + b1.x, p2.y + b1.y, p3.x + b1.z, p3.y + b1.w);
            float4* dst = (float4*)(y_out + (size_t)row * DIM + cc);
            dst[0] = lo; dst[1] = hi;
        }
    }
}

// ---------------- GRU cell (single block, 128 threads) ----------------
__global__ void gru_kernel(const float* __restrict__ cread,
                           const float* __restrict__ Wih, const float* __restrict__ Whh,
                           const float* __restrict__ bih, const float* __restrict__ bhh)
{
    __shared__ float c[DIM], hh[DIM];
    int tid = threadIdx.x;
    c[tid]  = cread[tid];
    hh[tid] = g_h[tid];
    __syncthreads();

    float gi[3], gh[3];
#pragma unroll
    for (int g = 0; g < 3; g++) {
        int row = g * DIM + tid;
        float si = bih[row], sh = bhh[row];
        const float* wi = Wih + (size_t)row * DIM;
        const float* wh = Whh + (size_t)row * DIM;
        for (int d = 0; d < DIM; d++) {
            si = fmaf(c[d],  wi[d], si);
            sh = fmaf(hh[d], wh[d], sh);
        }
        gi[g] = si; gh[g] = sh;
    }
    float r = 1.0f / (1.0f + expf(-(gi[0] + gh[0])));
    float z = 1.0f / (1.0f + expf(-(gi[1] + gh[1])));
    float n = tanhf(gi[2] + r * gh[2]);
    float hn = (1.0f - z) * n + z * hh[tid];
    __syncthreads();
    g_h[tid] = hn;
}

// ---------------- output head (single block, 256 threads) ----------------
__global__ void out_kernel(const float* __restrict__ Wo1, const float* __restrict__ bo1,
                           const float* __restrict__ Wo2, const float* __restrict__ bo2,
                           float* __restrict__ out)
{
    __shared__ float hs[DIM], tmp[2 * DIM];
    int tid = threadIdx.x;
    if (tid < DIM) hs[tid] = g_h[tid];
    __syncthreads();
    {
        float a = bo1[tid];
        const float* w = Wo1 + (size_t)tid * DIM;
        for (int d = 0; d < DIM; d++) a = fmaf(hs[d], w[d], a);
        tmp[tid] = fmaxf(a, 0.f);
    }
    __syncthreads();
    if (tid < VOC3) {
        float o = bo2[tid];
        const float* w = Wo2 + (size_t)tid * 2 * DIM;
        for (int j = 0; j < 2 * DIM; j++) o = fmaf(tmp[j], w[j], o);
        out[tid] = o;
    }
}

// =============================== host launcher ===============================
extern "C" void kernel_launch(void* const* d_in, const int* in_sizes, int n_in,
                              void* d_out, int out_size)
{
    const int*   c_diag_idx   = (const int*)  d_in[0];
    const int*   c_pro_idx    = (const int*)  d_in[1];
    const int*   c_edge_index = (const int*)  d_in[2];
    const int*   c_edge_type  = (const int*)  d_in[3];
    const float* diag_emb     = (const float*)d_in[4];
    const float* pro_emb      = (const float*)d_in[5];
    const float* W1           = (const float*)d_in[6];
    const float* root1        = (const float*)d_in[7];
    const float* b1           = (const float*)d_in[8];
    const float* W2           = (const float*)d_in[9];
    const float* root2        = (const float*)d_in[10];
    const float* b2           = (const float*)d_in[11];
    const float* gru_Wih      = (const float*)d_in[12];
    const float* gru_Whh      = (const float*)d_in[13];
    const float* gru_bih      = (const float*)d_in[14];
    const float* gru_bhh      = (const float*)d_in[15];
    const float* Wo1          = (const float*)d_in[16];
    const float* bo1          = (const float*)d_in[17];
    const float* Wo2          = (const float*)d_in[18];
    const float* bo2          = (const float*)d_in[19];
    float* out = (float*)d_out;

    void *p_x, *p_y, *p_xw, *p_tabm, *p_tabr, *p_map, *p_cnt, *p_off, *p_pos, *p_epk;
    void *p_blk, *p_blkoff, *p_cread, *p_h, *p_wbig;
    cudaGetSymbolAddress(&p_x,      g_x);
    cudaGetSymbolAddress(&p_y,      g_y);
    cudaGetSymbolAddress(&p_xw,     g_xw);
    cudaGetSymbolAddress(&p_tabm,   g_tabm);
    cudaGetSymbolAddress(&p_tabr,   g_tabr);
    cudaGetSymbolAddress(&p_map,    g_map);
    cudaGetSymbolAddress(&p_cnt,    g_cnt);
    cudaGetSymbolAddress(&p_off,    g_off);
    cudaGetSymbolAddress(&p_pos,    g_pos);
    cudaGetSymbolAddress(&p_epk,    g_epk);
    cudaGetSymbolAddress(&p_blk,    g_blk);
    cudaGetSymbolAddress(&p_blkoff, g_blkoff);
    cudaGetSymbolAddress(&p_cread,  g_cread);
    cudaGetSymbolAddress(&p_h,      g_h);
    cudaGetSymbolAddress(&p_wbig,   g_Wbig);

    float* wbig0 = (float*)p_wbig;
    float* wbig1 = wbig0 + DIM * NCOLS;

    // fork/join resources: created per call, intentionally NOT destroyed
    cudaStream_t s2;
    cudaStreamCreate(&s2);
    cudaEvent_t ev_fork, ev_join;
    cudaEventCreateWithFlags(&ev_fork, cudaEventDisableTiming);
    cudaEventCreateWithFlags(&ev_join, cudaEventDisableTiming);

    // ---- shared prologue on the capture (legacy) stream ----
    {
        int n = DIM * NCOLS;
        prep_wbig_kernel<<<(n + 255) / 256, 256>>>(W1, root1, wbig0);
        prep_wbig_kernel<<<(n + 255) / 256, 256>>>(W2, root2, wbig1);
    }
    tabgemm_kernel<<<dim3(TAB_GRID_X, TAB_GRID_Y), 256>>>(diag_emb, pro_emb, wbig0, b1);
    cudaMemsetAsync(p_h, 0, DIM * sizeof(float));

    // fork: s2 joins the capture, ordered after tab/wbig
    cudaEventRecord(ev_fork, 0);
    cudaStreamWaitEvent(s2, ev_fork, 0);

    // ---- per-visit pipelines: visit 0 on legacy stream, visit 1 on s2 ----
    for (int t = 0; t < T_VISITS; t++) {
        cudaStream_t st = (t == 0) ? (cudaStream_t)0 : s2;
        const int* diag_t = c_diag_idx + (size_t)t * N_DIAG;
        const int* pro_t  = c_pro_idx  + (size_t)t * N_PRO;
        const int* src_t  = c_edge_index + (size_t)t * 2 * N_EDGES;
        const int* dst_t  = src_t + N_EDGES;
        const int* et_t   = c_edge_type + (size_t)t * N_EDGES;

        float*          x_t      = (float*)p_x  + (size_t)t * N_NODES * DIM;
        float*          y_t      = (float*)p_y  + (size_t)t * N_NODES * DIM;
        __nv_bfloat16*  xw_t     = (__nv_bfloat16*)p_xw + (size_t)t * N_NODES * NRD;
        int*            map_t    = (int*)p_map  + (size_t)t * N_NODES;
        int*            cnt_t    = (int*)p_cnt  + (size_t)t * N_NODES * N_REL;
        int*            off_t    = (int*)p_off  + (size_t)t * (N_NODES + 1);
        int*            pos_t    = (int*)p_pos  + (size_t)t * N_NODES;
        int*            epk_t    = (int*)p_epk  + (size_t)t * N_EDGES;
        int*            blk_t    = (int*)p_blk  + (size_t)t * 64;
        int*            blkoff_t = (int*)p_blkoff + (size_t)t * 64;
        float*          cread_t  = (float*)p_cread + (size_t)t * DIM;

        map_kernel<<<(N_NODES + 255) / 256, 256, 0, st>>>(diag_t, pro_t, map_t);

        cudaMemsetAsync(cnt_t, 0, N_NODES * N_REL * sizeof(int), st);
        hist_kernel<<<(N_EDGES + 255) / 256, 256, 0, st>>>(dst_t, et_t, cnt_t);
        scan_block_kernel<<<SCAN_NBLK, SCAN_BLK, 0, st>>>(cnt_t, off_t, blk_t);
        scan_top_kernel<<<1, 64, 0, st>>>(blk_t, blkoff_t);
        scan_add_kernel<<<(N_NODES + 255) / 256, 256, 0, st>>>(off_t, pos_t, blkoff_t);
        scatter_kernel<<<(N_EDGES + 255) / 256, 256, 0, st>>>(src_t, dst_t, et_t,
                                                              map_t, pos_t, epk_t);
        cudaMemsetAsync(cread_t, 0, DIM * sizeof(float), st);

        // layer 1: bf16 message table + fp32 root table, CSR gather
        gather1_kernel<<<GATHER_BLOCKS, 256, 0, st>>>(
            (const __nv_bfloat16*)p_tabm, (const float*)p_tabr,
            off_t, cnt_t, epk_t, map_t, x_t);

        // layer 2: FFMA2 GEMM (bf16 xw out) + CSR gather with fused readout
        gemm_kernel<<<dim3(GEMM_GRID_X, GEMM_GRID_Y), 256, 0, st>>>(
            x_t, wbig1, b2, xw_t, y_t);
        gather2_kernel<<<GATHER_BLOCKS, 256, 0, st>>>(
            xw_t, off_t, cnt_t, epk_t, y_t, cread_t);
    }

    // join: legacy stream waits for visit 1
    cudaEventRecord(ev_join, s2);
    cudaStreamWaitEvent(0, ev_join, 0);

    // sequential GRU chain + head on legacy stream
    gru_kernel<<<1, DIM>>>((const float*)p_cread,       gru_Wih, gru_Whh, gru_bih, gru_bhh);
    gru_kernel<<<1, DIM>>>((const float*)p_cread + DIM, gru_Wih, gru_Whh, gru_bih, gru_bhh);
    out_kernel<<<1, 2 * DIM>>>(Wo1, bo1, Wo2, bo2, out);
}

// round 17
// speedup vs baseline: 2.8412x; 1.7573x over previous
#include <cuda_runtime.h>
#include <cuda_bf16.h>
#include <math.h>
#include <stdint.h>

#define DIM      128
#define N_DIAG   30000
#define N_PRO    20000
#define N_NODES  50000
#define N_EDGES  800000
#define N_REL    8
#define T_VISITS 2
#define NCOLS    (N_REL * DIM + DIM)   // 1152
#define NRD      (N_REL * DIM)         // 1024
#define VOC_DIAG 2000
#define VOC_PRO  1500
#define TAB_ROWS (VOC_DIAG + VOC_PRO)  // 3500
#define VOC3     150

// RULES LEARNED (hard way):
//  1. NO CUDA API calls before main().
//  2. NO register caps that cause spills (local-pool growth trips mem checkpoint).
//  3. From HOST code, pass device globals via cudaGetSymbolAddress, never by name.
//  4. Aggregate-first REGRESSED (+460us). Transform-first + CSR gather is right.
//  5. Two-stream overlap only hides wave TAILS; reduce per-kernel work instead.
//  6. Gathers are LATENCY-bound (bf16 tab gave ~0); stop shaving gather bytes.
//  7. This round: layer-2 GEMM moves to tensor pipe via tf32 mma.sync
//     (fp32 operands cvt'd in-register; ~5e-4 input rounding, ~5e-5 at output).
__device__ __align__(16) float          g_x  [2][N_NODES * DIM];
__device__ __align__(16) float          g_y  [2][N_NODES * DIM];
__device__ __align__(16) __nv_bfloat16  g_xw [2][(size_t)N_NODES * NRD];
__device__ __align__(16) __nv_bfloat16  g_tabm[TAB_ROWS * NRD];   // bf16 message table
__device__ __align__(16) float          g_tabr[TAB_ROWS * DIM];   // fp32 root+bias table
__device__ __align__(16) int            g_map[2][N_NODES];
__device__ __align__(16) int            g_cnt[2][N_NODES * N_REL];
__device__ __align__(16) int            g_off[2][N_NODES + 1];
__device__ __align__(16) int            g_pos[2][N_NODES];
__device__ __align__(16) int            g_epk[2][N_EDGES];
__device__ __align__(16) int            g_blk[2][64];
__device__ __align__(16) int            g_blkoff[2][64];
__device__ __align__(16) float          g_Wbig[2][DIM * NCOLS];
__device__ __align__(16) float          g_cread[2][DIM];
__device__ __align__(16) float          g_h[DIM];

// ---------------- tf32 mma helpers ----------------
__device__ __forceinline__ unsigned f2tf(float f)
{
    unsigned u;
    asm("cvt.rna.tf32.f32 %0, %1;" : "=r"(u) : "f"(f));
    return u;
}
__device__ __forceinline__ void mma_tf32(float* c, const unsigned* a, const unsigned* b)
{
    asm volatile(
        "mma.sync.aligned.m16n8k8.row.col.f32.tf32.tf32.f32 "
        "{%0,%1,%2,%3}, {%4,%5,%6,%7}, {%8,%9}, {%0,%1,%2,%3};"
        : "+f"(c[0]), "+f"(c[1]), "+f"(c[2]), "+f"(c[3])
        : "r"(a[0]), "r"(a[1]), "r"(a[2]), "r"(a[3]), "r"(b[0]), "r"(b[1]));
}

// ---------------- repack W: Wbig[d*1152 + c] = [W_r | root] ----------------
__global__ void prep_wbig_kernel(const float* __restrict__ W,
                                 const float* __restrict__ root,
                                 float* __restrict__ out)
{
    int idx = blockIdx.x * blockDim.x + threadIdx.x;
    if (idx >= DIM * NCOLS) return;
    int d = idx / NCOLS;
    int c = idx % NCOLS;
    float v;
    if (c < NRD) {
        int r = c >> 7, o = c & 127;
        v = W[(size_t)r * DIM * DIM + d * DIM + o];
    } else {
        v = root[d * DIM + (c - NRD)];
    }
    out[idx] = v;
}

// ---------------- node -> embedding-table row map ----------------
__global__ void map_kernel(const int* __restrict__ diag_idx,
                           const int* __restrict__ pro_idx,
                           int* __restrict__ map)
{
    int n = blockIdx.x * blockDim.x + threadIdx.x;
    if (n >= N_NODES) return;
    int m;
    if (n < N_DIAG) m = min(max(diag_idx[n], 0), VOC_DIAG - 1);
    else            m = VOC_DIAG + min(max(pro_idx[n - N_DIAG], 0), VOC_PRO - 1);
    map[n] = m;
}

// ---------------- histogram of (dst, etype) ----------------
__global__ void hist_kernel(const int* __restrict__ dst, const int* __restrict__ et,
                            int* __restrict__ cnt)
{
    int e = blockIdx.x * blockDim.x + threadIdx.x;
    if (e >= N_EDGES) return;
    int d = min(max(dst[e], 0), N_NODES - 1);
    int r = et[e] & (N_REL - 1);
    atomicAdd(&cnt[d * N_REL + r], 1);
}

// ---------------- 3-phase multi-block scan ----------------
#define SCAN_BLK 1024
#define SCAN_NBLK ((N_NODES + SCAN_BLK - 1) / SCAN_BLK)   // 49
__global__ __launch_bounds__(SCAN_BLK)
void scan_block_kernel(const int* __restrict__ cnt, int* __restrict__ off,
                       int* __restrict__ blk)
{
    __shared__ int sdata[SCAN_BLK];
    int tid = threadIdx.x;
    int d = blockIdx.x * SCAN_BLK + tid;
    int v = 0;
    if (d < N_NODES) {
#pragma unroll
        for (int r = 0; r < N_REL; r++) v += cnt[d * N_REL + r];
    }
    sdata[tid] = v;
    __syncthreads();
    for (int ofs = 1; ofs < SCAN_BLK; ofs <<= 1) {
        int t = (tid >= ofs) ? sdata[tid - ofs] : 0;
        __syncthreads();
        sdata[tid] += t;
        __syncthreads();
    }
    if (d < N_NODES) off[d] = sdata[tid] - v;
    if (tid == SCAN_BLK - 1) blk[blockIdx.x] = sdata[tid];
}
__global__ __launch_bounds__(64)
void scan_top_kernel(const int* __restrict__ blk, int* __restrict__ blkoff)
{
    __shared__ int s[64];
    int tid = threadIdx.x;
    s[tid] = (tid < SCAN_NBLK) ? blk[tid] : 0;
    __syncthreads();
    for (int ofs = 1; ofs < 64; ofs <<= 1) {
        int t = (tid >= ofs) ? s[tid - ofs] : 0;
        __syncthreads();
        s[tid] += t;
        __syncthreads();
    }
    int v = (tid < SCAN_NBLK) ? blk[tid] : 0;
    if (tid < SCAN_NBLK) blkoff[tid] = s[tid] - v;
}
__global__ void scan_add_kernel(int* __restrict__ off, int* __restrict__ pos,
                                const int* __restrict__ blkoff)
{
    int d = blockIdx.x * blockDim.x + threadIdx.x;
    if (d >= N_NODES) return;
    int o = off[d] + blkoff[d >> 10];
    off[d] = o;
    pos[d] = o;
    if (d == 0) off[N_NODES] = N_EDGES;
}

// ---------------- scatter edges into CSR; pack src|et|map[src] ----------------
__global__ void scatter_kernel(const int* __restrict__ src, const int* __restrict__ dst,
                               const int* __restrict__ et, const int* __restrict__ map,
                               int* __restrict__ pos, int* __restrict__ epk)
{
    int e = blockIdx.x * blockDim.x + threadIdx.x;
    if (e >= N_EDGES) return;
    int d = min(max(__ldg(dst + e), 0), N_NODES - 1);
    int s = min(max(__ldg(src + e), 0), N_NODES - 1);
    int r = __ldg(et + e) & (N_REL - 1);
    int m = __ldg(&map[s]);
    int p = atomicAdd(&pos[d], 1);
    epk[p] = s | (r << 16) | (m << 19);
}

// ---------------- layer-1 CSR gather: bf16 tabm rows, fp32 tabr base, writes x ----
#define GATHER_BLOCKS ((N_NODES + 7) / 8)     // 6250 exactly (50000/8)
__global__ __launch_bounds__(256)
void gather1_kernel(const __nv_bfloat16* __restrict__ TABM,
                    const float* __restrict__ TABR,
                    const int* __restrict__ off, const int* __restrict__ cnt,
                    const int* __restrict__ epk, const int* __restrict__ map,
                    float* __restrict__ xout)
{
    int gw   = (blockIdx.x * 256 + threadIdx.x) >> 5;
    int lane = threadIdx.x & 31;
    const int d = gw;

    int b  = __ldg(&off[d]);
    int e2 = __ldg(&off[d + 1]);

    float nv = 0.f;
    if (lane < N_REL) {
        int c = __ldg(&cnt[d * N_REL + lane]);
        nv = 1.0f / (float)max(c, 1);
    }

    float4 acc = make_float4(0.f, 0.f, 0.f, 0.f);

#define GACC1(pk) do {                                                        \
        int s_ = (pk) >> 19;                                                   \
        int r_ = ((pk) >> 16) & 7;                                            \
        float nm = __shfl_sync(0xFFFFFFFFu, nv, r_);                           \
        uint2 u_ = *(const uint2*)(TABM + (size_t)s_ * NRD + r_ * DIM + lane*4);\
        float2 f0 = __bfloat1622float2(*(const __nv_bfloat162*)&u_.x);         \
        float2 f1 = __bfloat1622float2(*(const __nv_bfloat162*)&u_.y);         \
        acc.x += f0.x * nm; acc.y += f0.y * nm;                                \
        acc.z += f1.x * nm; acc.w += f1.y * nm;                                \
    } while (0)

    int i = b;
    for (; i + 8 <= e2; i += 8) {
        int pk0 = __ldg(epk + i + 0);
        int pk1 = __ldg(epk + i + 1);
        int pk2 = __ldg(epk + i + 2);
        int pk3 = __ldg(epk + i + 3);
        int pk4 = __ldg(epk + i + 4);
        int pk5 = __ldg(epk + i + 5);
        int pk6 = __ldg(epk + i + 6);
        int pk7 = __ldg(epk + i + 7);
        GACC1(pk0); GACC1(pk1); GACC1(pk2); GACC1(pk3);
        GACC1(pk4); GACC1(pk5); GACC1(pk6); GACC1(pk7);
    }
    for (; i + 4 <= e2; i += 4) {
        int pk0 = __ldg(epk + i + 0);
        int pk1 = __ldg(epk + i + 1);
        int pk2 = __ldg(epk + i + 2);
        int pk3 = __ldg(epk + i + 3);
        GACC1(pk0); GACC1(pk1); GACC1(pk2); GACC1(pk3);
    }
    for (; i < e2; i++) { int pk = __ldg(epk + i); GACC1(pk); }
#undef GACC1

    int m = __ldg(&map[d]);
    float4 base = *(const float4*)(TABR + (size_t)m * DIM + lane * 4);
    float4 o;
    o.x = fmaxf(base.x + acc.x, 0.f);
    o.y = fmaxf(base.y + acc.y, 0.f);
    o.z = fmaxf(base.z + acc.z, 0.f);
    o.w = fmaxf(base.w + acc.w, 0.f);
    *(float4*)(xout + (size_t)d * DIM + lane * 4) = o;
}

// ---------------- layer-2 CSR gather: bf16 xw rows, folds readout, no x store ----
__global__ __launch_bounds__(256)
void gather2_kernel(const __nv_bfloat16* __restrict__ XW,
                    const int* __restrict__ off, const int* __restrict__ cnt,
                    const int* __restrict__ epk,
                    const float* __restrict__ ybase, float* __restrict__ cread)
{
    __shared__ float scol[DIM];
    int tid  = threadIdx.x;
    if (tid < DIM) scol[tid] = 0.f;
    __syncthreads();

    int gw   = (blockIdx.x * 256 + tid) >> 5;
    int lane = tid & 31;
    const int d = gw;

    int b  = __ldg(&off[d]);
    int e2 = __ldg(&off[d + 1]);

    float nv = 0.f;
    if (lane < N_REL) {
        int c = __ldg(&cnt[d * N_REL + lane]);
        nv = 1.0f / (float)max(c, 1);
    }

    float4 acc = make_float4(0.f, 0.f, 0.f, 0.f);

#define GACC2(pk) do {                                                       \
        int s_ = (pk) & 0xFFFF;                                               \
        int r_ = ((pk) >> 16) & 7;                                           \
        float nm = __shfl_sync(0xFFFFFFFFu, nv, r_);                          \
        uint2 u_ = *(const uint2*)(XW + (size_t)s_ * NRD + r_ * DIM + lane*4);\
        float2 f0 = __bfloat1622float2(*(const __nv_bfloat162*)&u_.x);        \
        float2 f1 = __bfloat1622float2(*(const __nv_bfloat162*)&u_.y);        \
        acc.x += f0.x * nm; acc.y += f0.y * nm;                               \
        acc.z += f1.x * nm; acc.w += f1.y * nm;                               \
    } while (0)

    int i = b;
    for (; i + 8 <= e2; i += 8) {
        int pk0 = __ldg(epk + i + 0);
        int pk1 = __ldg(epk + i + 1);
        int pk2 = __ldg(epk + i + 2);
        int pk3 = __ldg(epk + i + 3);
        int pk4 = __ldg(epk + i + 4);
        int pk5 = __ldg(epk + i + 5);
        int pk6 = __ldg(epk + i + 6);
        int pk7 = __ldg(epk + i + 7);
        GACC2(pk0); GACC2(pk1); GACC2(pk2); GACC2(pk3);
        GACC2(pk4); GACC2(pk5); GACC2(pk6); GACC2(pk7);
    }
    for (; i + 4 <= e2; i += 4) {
        int pk0 = __ldg(epk + i + 0);
        int pk1 = __ldg(epk + i + 1);
        int pk2 = __ldg(epk + i + 2);
        int pk3 = __ldg(epk + i + 3);
        GACC2(pk0); GACC2(pk1); GACC2(pk2); GACC2(pk3);
    }
    for (; i < e2; i++) { int pk = __ldg(epk + i); GACC2(pk); }
#undef GACC2

    float4 base = *(const float4*)(ybase + (size_t)d * DIM + lane * 4);
    float ox = fmaxf(base.x + acc.x, 0.f);
    float oy = fmaxf(base.y + acc.y, 0.f);
    float oz = fmaxf(base.z + acc.z, 0.f);
    float ow = fmaxf(base.w + acc.w, 0.f);

    atomicAdd(&scol[lane * 4 + 0], ox);
    atomicAdd(&scol[lane * 4 + 1], oy);
    atomicAdd(&scol[lane * 4 + 2], oz);
    atomicAdd(&scol[lane * 4 + 3], ow);
    __syncthreads();
    if (tid < DIM) atomicAdd(&cread[tid], scol[tid]);
}

// ======== table GEMM: splits output into bf16 message table + fp32 root table ====
#define T_BM 128
#define T_BN 64
#define T_BK 32
#define TAB_GRID_X (NCOLS / T_BN)                      // 18
#define TAB_GRID_Y ((TAB_ROWS + T_BM - 1) / T_BM)      // 28
__global__ __launch_bounds__(256)
void tabgemm_kernel(const float* __restrict__ diag_emb,
                    const float* __restrict__ pro_emb,
                    const float* __restrict__ Bmat,
                    const float* __restrict__ bias)
{
    __shared__ float As[T_BK][T_BM + 4];
    __shared__ float Bs[T_BK][T_BN];

    const int block_m = blockIdx.y * T_BM;
    const int block_n = blockIdx.x * T_BN;
    const int tid = threadIdx.x;
    const int tx = tid & 15;
    const int ty = tid >> 4;

    float acc[8][4];
#pragma unroll
    for (int m = 0; m < 8; m++)
#pragma unroll
        for (int n = 0; n < 4; n++) acc[m][n] = 0.f;

    for (int kb = 0; kb < DIM; kb += T_BK) {
#pragma unroll
        for (int i = 0; i < 4; i++) {
            int fid = tid + i * 256;
            int r   = fid >> 3;
            int c   = (fid & 7) * 4;
            int row = block_m + r;
            float4 v = make_float4(0.f, 0.f, 0.f, 0.f);
            if (row < TAB_ROWS) {
                const float* srow = (row < VOC_DIAG)
                    ? diag_emb + (size_t)row * DIM
                    : pro_emb  + (size_t)(row - VOC_DIAG) * DIM;
                v = *(const float4*)(srow + kb + c);
            }
            As[c + 0][r] = v.x; As[c + 1][r] = v.y;
            As[c + 2][r] = v.z; As[c + 3][r] = v.w;
        }
#pragma unroll
        for (int i = 0; i < 2; i++) {
            int fid = tid + i * 256;
            int r   = fid >> 4;
            int c   = (fid & 15) * 4;
            *(float4*)(&Bs[r][c]) =
                *(const float4*)(Bmat + (size_t)(kb + r) * NCOLS + block_n + c);
        }
        __syncthreads();

#pragma unroll
        for (int k = 0; k < T_BK; k++) {
            float4 a0 = *(const float4*)(&As[k][ty * 8]);
            float4 a1 = *(const float4*)(&As[k][ty * 8 + 4]);
            float4 b  = *(const float4*)(&Bs[k][tx * 4]);
            float am[8] = {a0.x, a0.y, a0.z, a0.w, a1.x, a1.y, a1.z, a1.w};
#pragma unroll
            for (int m = 0; m < 8; m++) {
                acc[m][0] = fmaf(am[m], b.x, acc[m][0]);
                acc[m][1] = fmaf(am[m], b.y, acc[m][1]);
                acc[m][2] = fmaf(am[m], b.z, acc[m][2]);
                acc[m][3] = fmaf(am[m], b.w, acc[m][3]);
            }
        }
        __syncthreads();
    }

    const int col = block_n + tx * 4;
#pragma unroll
    for (int m = 0; m < 8; m++) {
        int row = block_m + ty * 8 + m;
        if (row >= TAB_ROWS) continue;
        if (col < NRD) {
            __nv_bfloat162 q0 = __floats2bfloat162_rn(acc[m][0], acc[m][1]);
            __nv_bfloat162 q1 = __floats2bfloat162_rn(acc[m][2], acc[m][3]);
            uint2 pk;
            pk.x = *(unsigned int*)&q0; pk.y = *(unsigned int*)&q1;
            *(uint2*)(g_tabm + (size_t)row * NRD + col) = pk;
        } else {
            int cc = col - NRD;
            float4 bv = *(const float4*)(bias + cc);
            float4 v = make_float4(acc[m][0] + bv.x, acc[m][1] + bv.y,
                                   acc[m][2] + bv.z, acc[m][3] + bv.w);
            *(float4*)(g_tabr + (size_t)row * DIM + cc) = v;
        }
    }
}

// ======== layer-2 GEMM: tf32 mma.sync tensor-core edition ==========
// [50000,128] x [128,1152]; 128x128x32 tile, 8 warps (2x4), warp tile 64x32.
// Fragments loaded directly from padded smem (conflict-free strides), operands
// cvt.rna.tf32 in-register. Epilogue identical to R16 (bf16 xw / fp32 y+bias).
#define BM 128
#define BN 128
#define BK 32
#define AS_STR (BK + 4)     // 36 floats: frag banks (4*row+k)%32 all distinct
#define BS_STR (BN + 8)     // 136 floats: frag banks (8*k+col)%32 all distinct
#define GEMM_GRID_X (NCOLS / BN)                       // 9
#define GEMM_GRID_Y ((N_NODES + BM - 1) / BM)          // 391
__global__ __launch_bounds__(256)
void gemm_kernel(const float* __restrict__ A, const float* __restrict__ B,
                 const float* __restrict__ bias,
                 __nv_bfloat16* __restrict__ xw_out, float* __restrict__ y_out)
{
    __shared__ float As[BM][AS_STR];
    __shared__ float Bs[BK][BS_STR];

    const int block_m = blockIdx.y * BM;
    const int block_n = blockIdx.x * BN;
    const int tid  = threadIdx.x;
    const int lane = tid & 31;
    const int wid  = tid >> 5;
    const int wm   = wid >> 2;          // 0..1
    const int wn   = wid & 3;           // 0..3
    const int grp  = lane >> 2;         // 0..7
    const int qid  = lane & 3;          // 0..3

    float acc[4][4][4];
#pragma unroll
    for (int mt = 0; mt < 4; mt++)
#pragma unroll
        for (int nt = 0; nt < 4; nt++)
#pragma unroll
            for (int j = 0; j < 4; j++) acc[mt][nt][j] = 0.f;

    for (int kb = 0; kb < DIM; kb += BK) {
        // A tile: 128x32 f32 -> 1024 float4 over 256 threads (4 each)
#pragma unroll
        for (int i = 0; i < 4; i++) {
            int fid = tid + i * 256;
            int r   = fid >> 3;               // 0..127
            int c   = (fid & 7) * 4;          // 0,4,...,28
            float4 v = make_float4(0.f, 0.f, 0.f, 0.f);
            if (block_m + r < N_NODES)
                v = *(const float4*)(A + (size_t)(block_m + r) * DIM + kb + c);
            *(float4*)(&As[r][c]) = v;        // AS_STR=36 (mult of 4): aligned
        }
        // B tile: 32x128 f32 -> 1024 float4 over 256 threads (4 each)
#pragma unroll
        for (int i = 0; i < 4; i++) {
            int fid = tid + i * 256;
            int r   = fid >> 5;               // 0..31
            int c   = (fid & 31) * 4;         // 0..124
            *(float4*)(&Bs[r][c]) =
                *(const float4*)(B + (size_t)(kb + r) * NCOLS + block_n + c);
        }
        __syncthreads();

#pragma unroll
        for (int ks = 0; ks < BK / 8; ks++) {
            const int k0 = ks * 8;
            unsigned afr[4][4];
#pragma unroll
            for (int mt = 0; mt < 4; mt++) {
                int row = wm * 64 + mt * 16 + grp;
                afr[mt][0] = f2tf(As[row    ][k0 + qid    ]);
                afr[mt][1] = f2tf(As[row + 8][k0 + qid    ]);
                afr[mt][2] = f2tf(As[row    ][k0 + qid + 4]);
                afr[mt][3] = f2tf(As[row + 8][k0 + qid + 4]);
            }
            unsigned bfr[4][2];
#pragma unroll
            for (int nt = 0; nt < 4; nt++) {
                int col = wn * 32 + nt * 8 + grp;
                bfr[nt][0] = f2tf(Bs[k0 + qid    ][col]);
                bfr[nt][1] = f2tf(Bs[k0 + qid + 4][col]);
            }
#pragma unroll
            for (int mt = 0; mt < 4; mt++)
#pragma unroll
                for (int nt = 0; nt < 4; nt++)
                    mma_tf32(acc[mt][nt], afr[mt], bfr[nt]);
        }
        __syncthreads();
    }

    // epilogue: c0/c1 -> (row, col..col+1); c2/c3 -> (row+8, col..col+1)
    const bool is_root = (block_n >= NRD);    // block 8 only
#pragma unroll
    for (int mt = 0; mt < 4; mt++) {
#pragma unroll
        for (int nt = 0; nt < 4; nt++) {
            int row0 = block_m + wm * 64 + mt * 16 + grp;
            int col  = block_n + wn * 32 + nt * 8 + qid * 2;
#pragma unroll
            for (int h = 0; h < 2; h++) {
                int row = row0 + h * 8;
                if (row >= N_NODES) continue;
                float v0 = acc[mt][nt][h * 2 + 0];
                float v1 = acc[mt][nt][h * 2 + 1];
                if (!is_root) {
                    __nv_bfloat162 q = __floats2bfloat162_rn(v0, v1);
                    *(unsigned int*)(xw_out + (size_t)row * NRD + col) =
                        *(unsigned int*)&q;
                } else {
                    int cc = col - NRD;
                    float2 o = make_float2(v0 + bias[cc], v1 + bias[cc + 1]);
                    *(float2*)(y_out + (size_t)row * DIM + cc) = o;
                }
            }
        }
    }
}

// ---------------- GRU cell (single block, 128 threads) ----------------
__global__ void gru_kernel(const float* __restrict__ cread,
                           const float* __restrict__ Wih, const float* __restrict__ Whh,
                           const float* __restrict__ bih, const float* __restrict__ bhh)
{
    __shared__ float c[DIM], hh[DIM];
    int tid = threadIdx.x;
    c[tid]  = cread[tid];
    hh[tid] = g_h[tid];
    __syncthreads();

    float gi[3], gh[3];
#pragma unroll
    for (int g = 0; g < 3; g++) {
        int row = g * DIM + tid;
        float si = bih[row], sh = bhh[row];
        const float* wi = Wih + (size_t)row * DIM;
        const float* wh = Whh + (size_t)row * DIM;
        for (int d = 0; d < DIM; d++) {
            si = fmaf(c[d],  wi[d], si);
            sh = fmaf(hh[d], wh[d], sh);
        }
        gi[g] = si; gh[g] = sh;
    }
    float r = 1.0f / (1.0f + expf(-(gi[0] + gh[0])));
    float z = 1.0f / (1.0f + expf(-(gi[1] + gh[1])));
    float n = tanhf(gi[2] + r * gh[2]);
    float hn = (1.0f - z) * n + z * hh[tid];
    __syncthreads();
    g_h[tid] = hn;
}

// ---------------- output head (single block, 256 threads) ----------------
__global__ void out_kernel(const float* __restrict__ Wo1, const float* __restrict__ bo1,
                           const float* __restrict__ Wo2, const float* __restrict__ bo2,
                           float* __restrict__ out)
{
    __shared__ float hs[DIM], tmp[2 * DIM];
    int tid = threadIdx.x;
    if (tid < DIM) hs[tid] = g_h[tid];
    __syncthreads();
    {
        float a = bo1[tid];
        const float* w = Wo1 + (size_t)tid * DIM;
        for (int d = 0; d < DIM; d++) a = fmaf(hs[d], w[d], a);
        tmp[tid] = fmaxf(a, 0.f);
    }
    __syncthreads();
    if (tid < VOC3) {
        float o = bo2[tid];
        const float* w = Wo2 + (size_t)tid * 2 * DIM;
        for (int j = 0; j < 2 * DIM; j++) o = fmaf(tmp[j], w[j], o);
        out[tid] = o;
    }
}

// =============================== host launcher ===============================
extern "C" void kernel_launch(void* const* d_in, const int* in_sizes, int n_in,
                              void* d_out, int out_size)
{
    const int*   c_diag_idx   = (const int*)  d_in[0];
    const int*   c_pro_idx    = (const int*)  d_in[1];
    const int*   c_edge_index = (const int*)  d_in[2];
    const int*   c_edge_type  = (const int*)  d_in[3];
    const float* diag_emb     = (const float*)d_in[4];
    const float* pro_emb      = (const float*)d_in[5];
    const float* W1           = (const float*)d_in[6];
    const float* root1        = (const float*)d_in[7];
    const float* b1           = (const float*)d_in[8];
    const float* W2           = (const float*)d_in[9];
    const float* root2        = (const float*)d_in[10];
    const float* b2           = (const float*)d_in[11];
    const float* gru_Wih      = (const float*)d_in[12];
    const float* gru_Whh      = (const float*)d_in[13];
    const float* gru_bih      = (const float*)d_in[14];
    const float* gru_bhh      = (const float*)d_in[15];
    const float* Wo1          = (const float*)d_in[16];
    const float* bo1          = (const float*)d_in[17];
    const float* Wo2          = (const float*)d_in[18];
    const float* bo2          = (const float*)d_in[19];
    float* out = (float*)d_out;

    void *p_x, *p_y, *p_xw, *p_tabm, *p_tabr, *p_map, *p_cnt, *p_off, *p_pos, *p_epk;
    void *p_blk, *p_blkoff, *p_cread, *p_h, *p_wbig;
    cudaGetSymbolAddress(&p_x,      g_x);
    cudaGetSymbolAddress(&p_y,      g_y);
    cudaGetSymbolAddress(&p_xw,     g_xw);
    cudaGetSymbolAddress(&p_tabm,   g_tabm);
    cudaGetSymbolAddress(&p_tabr,   g_tabr);
    cudaGetSymbolAddress(&p_map,    g_map);
    cudaGetSymbolAddress(&p_cnt,    g_cnt);
    cudaGetSymbolAddress(&p_off,    g_off);
    cudaGetSymbolAddress(&p_pos,    g_pos);
    cudaGetSymbolAddress(&p_epk,    g_epk);
    cudaGetSymbolAddress(&p_blk,    g_blk);
    cudaGetSymbolAddress(&p_blkoff, g_blkoff);
    cudaGetSymbolAddress(&p_cread,  g_cread);
    cudaGetSymbolAddress(&p_h,      g_h);
    cudaGetSymbolAddress(&p_wbig,   g_Wbig);

    float* wbig0 = (float*)p_wbig;
    float* wbig1 = wbig0 + DIM * NCOLS;

    // fork/join resources: created per call, intentionally NOT destroyed
    cudaStream_t s2;
    cudaStreamCreate(&s2);
    cudaEvent_t ev_fork, ev_join;
    cudaEventCreateWithFlags(&ev_fork, cudaEventDisableTiming);
    cudaEventCreateWithFlags(&ev_join, cudaEventDisableTiming);

    // ---- shared prologue on the capture (legacy) stream ----
    {
        int n = DIM * NCOLS;
        prep_wbig_kernel<<<(n + 255) / 256, 256>>>(W1, root1, wbig0);
        prep_wbig_kernel<<<(n + 255) / 256, 256>>>(W2, root2, wbig1);
    }
    tabgemm_kernel<<<dim3(TAB_GRID_X, TAB_GRID_Y), 256>>>(diag_emb, pro_emb, wbig0, b1);
    cudaMemsetAsync(p_h, 0, DIM * sizeof(float));

    // fork: s2 joins the capture, ordered after tab/wbig
    cudaEventRecord(ev_fork, 0);
    cudaStreamWaitEvent(s2, ev_fork, 0);

    // ---- per-visit pipelines: visit 0 on legacy stream, visit 1 on s2 ----
    for (int t = 0; t < T_VISITS; t++) {
        cudaStream_t st = (t == 0) ? (cudaStream_t)0 : s2;
        const int* diag_t = c_diag_idx + (size_t)t * N_DIAG;
        const int* pro_t  = c_pro_idx  + (size_t)t * N_PRO;
        const int* src_t  = c_edge_index + (size_t)t * 2 * N_EDGES;
        const int* dst_t  = src_t + N_EDGES;
        const int* et_t   = c_edge_type + (size_t)t * N_EDGES;

        float*          x_t      = (float*)p_x  + (size_t)t * N_NODES * DIM;
        float*          y_t      = (float*)p_y  + (size_t)t * N_NODES * DIM;
        __nv_bfloat16*  xw_t     = (__nv_bfloat16*)p_xw + (size_t)t * N_NODES * NRD;
        int*            map_t    = (int*)p_map  + (size_t)t * N_NODES;
        int*            cnt_t    = (int*)p_cnt  + (size_t)t * N_NODES * N_REL;
        int*            off_t    = (int*)p_off  + (size_t)t * (N_NODES + 1);
        int*            pos_t    = (int*)p_pos  + (size_t)t * N_NODES;
        int*            epk_t    = (int*)p_epk  + (size_t)t * N_EDGES;
        int*            blk_t    = (int*)p_blk  + (size_t)t * 64;
        int*            blkoff_t = (int*)p_blkoff + (size_t)t * 64;
        float*          cread_t  = (float*)p_cread + (size_t)t * DIM;

        map_kernel<<<(N_NODES + 255) / 256, 256, 0, st>>>(diag_t, pro_t, map_t);

        cudaMemsetAsync(cnt_t, 0, N_NODES * N_REL * sizeof(int), st);
        hist_kernel<<<(N_EDGES + 255) / 256, 256, 0, st>>>(dst_t, et_t, cnt_t);
        scan_block_kernel<<<SCAN_NBLK, SCAN_BLK, 0, st>>>(cnt_t, off_t, blk_t);
        scan_top_kernel<<<1, 64, 0, st>>>(blk_t, blkoff_t);
        scan_add_kernel<<<(N_NODES + 255) / 256, 256, 0, st>>>(off_t, pos_t, blkoff_t);
        scatter_kernel<<<(N_EDGES + 255) / 256, 256, 0, st>>>(src_t, dst_t, et_t,
                                                              map_t, pos_t, epk_t);
        cudaMemsetAsync(cread_t, 0, DIM * sizeof(float), st);

        // layer 1: bf16 message table + fp32 root table, CSR gather
        gather1_kernel<<<GATHER_BLOCKS, 256, 0, st>>>(
            (const __nv_bfloat16*)p_tabm, (const float*)p_tabr,
            off_t, cnt_t, epk_t, map_t, x_t);

        // layer 2: tf32 tensor-core GEMM + CSR gather with fused readout
        gemm_kernel<<<dim3(GEMM_GRID_X, GEMM_GRID_Y), 256, 0, st>>>(
            x_t, wbig1, b2, xw_t, y_t);
        gather2_kernel<<<GATHER_BLOCKS, 256, 0, st>>>(
            xw_t, off_t, cnt_t, epk_t, y_t, cread_t);
    }

    // join: legacy stream waits for visit 1
    cudaEventRecord(ev_join, s2);
    cudaStreamWaitEvent(0, ev_join, 0);

    // sequential GRU chain + head on legacy stream
    gru_kernel<<<1, DIM>>>((const float*)p_cread,       gru_Wih, gru_Whh, gru_bih, gru_bhh);
    gru_kernel<<<1, DIM>>>((const float*)p_cread + DIM, gru_Wih, gru_Whh, gru_bih, gru_bhh);
    out_kernel<<<1, 2 * DIM>>>(Wo1, bo1, Wo2, bo2, out);
}